// round 5
// baseline (speedup 1.0000x reference)
#include <cuda_runtime.h>
#include <stdint.h>
#include <math.h>

// Problem constants
#define BB 16
#define CC 512
#define NN 2304      // 48*48
#define II 64

// ---------------- scratch (static device globals; no allocation) ----------------
__device__ float g_qk[(size_t)BB * 128 * NN];        // 18 MB: q rows 0-63, k rows 64-127
__device__ float g_v[(size_t)BB * CC * NN];          // 72 MB (tf32-rounded)
__device__ float g_s[(size_t)BB * NN * NN];          // 324 MB (S, then tf32-rounded P)
__device__ float g_wqk[128 * CC];                    // [Wq; Wk] concat (fp32)
__device__ float g_wvr[CC * CC];                     // Wv tf32-rounded

// =====================================================================
// helpers
// =====================================================================
__device__ __forceinline__ uint32_t smem_u32(const void* p) {
    uint32_t a;
    asm("{ .reg .u64 t; cvta.to.shared.u64 t, %1; cvt.u32.u64 %0, t; }"
        : "=r"(a) : "l"(p));
    return a;
}

__device__ __forceinline__ void cp_async16(uint32_t saddr, const void* gptr) {
    asm volatile("cp.async.cg.shared.global [%0], [%1], 16;"
                 :: "r"(saddr), "l"(gptr) : "memory");
}
__device__ __forceinline__ void cp_commit() {
    asm volatile("cp.async.commit_group;" ::: "memory");
}
template<int N>
__device__ __forceinline__ void cp_wait() {
    asm volatile("cp.async.wait_group %0;" :: "n"(N) : "memory");
}

__device__ __forceinline__ uint32_t f2tf32(float f) {
    uint32_t u;
    asm("cvt.rna.tf32.f32 %0, %1;" : "=r"(u) : "f"(f));
    return u;
}

// D += A(16x8, row) * B(8x8, col); fp32 accumulate, tf32 operands
__device__ __forceinline__ void mma16888(float* d, const uint32_t* a, const uint32_t* b) {
    asm volatile(
        "mma.sync.aligned.m16n8k8.row.col.f32.tf32.tf32.f32 "
        "{%0,%1,%2,%3}, {%4,%5,%6,%7}, {%8,%9}, {%0,%1,%2,%3};"
        : "+f"(d[0]), "+f"(d[1]), "+f"(d[2]), "+f"(d[3])
        : "r"(a[0]), "r"(a[1]), "r"(a[2]), "r"(a[3]), "r"(b[0]), "r"(b[1]));
}

// =====================================================================
// prep: concat [Wq; Wk] (fp32) and round Wv to tf32
// =====================================================================
__global__ void prep_kernel(const float* __restrict__ Wq, const float* __restrict__ Wk,
                            const float* __restrict__ Wv)
{
    const int i = blockIdx.x * blockDim.x + threadIdx.x;
    if (i < 128 * CC)
        g_wqk[i] = (i < II * CC) ? Wq[i] : Wk[i - II * CC];
    if (i < CC * CC)
        g_wvr[i] = __uint_as_float(f2tf32(Wv[i]));
}

// =====================================================================
// O = gamma * (V @ P^T) + X via mma.sync tf32
// Operands pre-rounded to tf32 bit patterns: NO cvt in the inner loop.
// C[m,n] = sum_k V[m,k] * P[n,k]; both K-contiguous (row.col / NT)
// CTA tile 128x128, K chunks of 16, 4-stage cp.async ring.
// =====================================================================
#define OSTR 20                     // smem row stride (floats), conflict-free frags
#define OTILE (128 * OSTR)          // floats per operand tile
#define OSTAGE (2 * OTILE)          // A + B per stage
#define ONCH (NN / 16)              // 144 k-chunks
#define OV_SMEM (4 * OSTAGE * 4)    // bytes: 81920

__global__ __launch_bounds__(256, 2)
void ov_mma_kernel(const float* __restrict__ V, const float* __restrict__ P,
                   const float* __restrict__ X, float* __restrict__ O,
                   const float* __restrict__ gamma_p)
{
    extern __shared__ float sm[];

    const int tid = threadIdx.x;
    const long long bz = blockIdx.z;
    const float* Vb = V + bz * (long long)(CC * NN);
    const float* Pb = P + bz * (long long)(NN * NN);
    const float* Xb = X + bz * (long long)(CC * NN);
    float*       Ob = O + bz * (long long)(CC * NN);

    const int m0 = blockIdx.y * 128;
    const int n0 = blockIdx.x * 128;

    const int lrow = tid >> 1;
    const int lc   = (tid & 1) * 8;
    const float* gA = Vb + (long long)(m0 + lrow) * NN + lc;
    const float* gB = Pb + (long long)(n0 + lrow) * NN + lc;
    const uint32_t sbase = smem_u32(sm);
    const uint32_t sA_st = sbase + (uint32_t)(lrow * OSTR + lc) * 4u;
    const uint32_t sB_st = sA_st + OTILE * 4u;

#define OV_ISSUE(c)                                                        \
    do {                                                                   \
        const uint32_t off_ = (uint32_t)((c) & 3) * (OSTAGE * 4u);         \
        const float* pa_ = gA + (c) * 16;                                  \
        const float* pb_ = gB + (c) * 16;                                  \
        cp_async16(sA_st + off_,      pa_);                                \
        cp_async16(sA_st + off_ + 16, pa_ + 4);                            \
        cp_async16(sB_st + off_,      pb_);                                \
        cp_async16(sB_st + off_ + 16, pb_ + 4);                            \
        cp_commit();                                                       \
    } while (0)

    OV_ISSUE(0); OV_ISSUE(1); OV_ISSUE(2);

    const int wid  = tid >> 5, lane = tid & 31;
    const int wm   = (wid >> 2) * 64;
    const int wn   = (wid & 3) * 32;
    const int g4   = lane >> 2;
    const int tg   = lane & 3;

    float acc[4][4][4];
    #pragma unroll
    for (int i = 0; i < 4; i++)
        #pragma unroll
        for (int j = 0; j < 4; j++)
            #pragma unroll
            for (int r = 0; r < 4; r++) acc[i][j][r] = 0.f;

    for (int c = 0; c < ONCH; c++) {
        if (c + 2 < ONCH)       cp_wait<2>();
        else if (c + 1 < ONCH)  cp_wait<1>();
        else                    cp_wait<0>();
        __syncthreads();

        if (c + 3 < ONCH) OV_ISSUE(c + 3);

        const float* A_ = sm + (c & 3) * OSTAGE;
        const float* B_ = A_ + OTILE;

        #pragma unroll
        for (int s = 0; s < 2; s++) {
            const int kk = s * 8 + tg;
            uint32_t a[4][4], b[4][2];
            #pragma unroll
            for (int mt = 0; mt < 4; mt++) {
                const int r0 = wm + mt * 16 + g4;
                a[mt][0] = __float_as_uint(A_[r0 * OSTR + kk]);
                a[mt][1] = __float_as_uint(A_[(r0 + 8) * OSTR + kk]);
                a[mt][2] = __float_as_uint(A_[r0 * OSTR + kk + 4]);
                a[mt][3] = __float_as_uint(A_[(r0 + 8) * OSTR + kk + 4]);
            }
            #pragma unroll
            for (int nt = 0; nt < 4; nt++) {
                const int nr = wn + nt * 8 + g4;
                b[nt][0] = __float_as_uint(B_[nr * OSTR + kk]);
                b[nt][1] = __float_as_uint(B_[nr * OSTR + kk + 4]);
            }
            #pragma unroll
            for (int mt = 0; mt < 4; mt++)
                #pragma unroll
                for (int nt = 0; nt < 4; nt++)
                    mma16888(acc[mt][nt], a[mt], b[nt]);
        }
    }

    const float g = *gamma_p;
    #pragma unroll
    for (int mt = 0; mt < 4; mt++) {
        #pragma unroll
        for (int half = 0; half < 2; half++) {
            const int m = m0 + wm + mt * 16 + g4 + half * 8;
            const long long rb = (long long)m * NN;
            #pragma unroll
            for (int nt = 0; nt < 4; nt++) {
                const int n = n0 + wn + nt * 8 + 2 * tg;
                float2 xr = *(const float2*)(Xb + rb + n);
                float2 o;
                o.x = fmaf(g, acc[mt][nt][half * 2 + 0], xr.x);
                o.y = fmaf(g, acc[mt][nt][half * 2 + 1], xr.y);
                *(float2*)(Ob + rb + n) = o;
            }
        }
    }
#undef OV_ISSUE
}

// =====================================================================
// v = Wv @ x via mma.sync tf32; output stored tf32-rounded.
// C[c,n] = sum_k Wv[c,k] * x[k,n]. A (Wv, pre-rounded) K-contiguous;
// B (x) staged [k][n] with row stride 136 (conflict-free col frags),
// x fragments converted with cvt.rna at load.
// =====================================================================
#define VBSTR 136                    // B smem row stride (floats): 8*tg+g4 distinct
#define VATILE (128 * OSTR)          // 2560 floats
#define VBTILE (16 * VBSTR)          // 2176 floats
#define VSTAGE (VATILE + VBTILE)     // 4736 floats
#define VNCH (CC / 16)               // 32 k-chunks
#define VX_SMEM (4 * VSTAGE * 4)     // 75776 bytes

__global__ __launch_bounds__(256, 2)
void vx_mma_kernel(const float* __restrict__ Wvr, const float* __restrict__ x,
                   float* __restrict__ Vout)
{
    extern __shared__ float sm[];

    const int tid = threadIdx.x;
    const long long bz = blockIdx.z;
    const float* xb = x + bz * (long long)(CC * NN);
    float*       Vb = Vout + bz * (long long)(CC * NN);

    const int m0 = blockIdx.y * 128;
    const int n0 = blockIdx.x * 128;

    // A staging: thread t -> row t>>1, 8-float half (t&1)*8
    const int arow = tid >> 1;
    const int ac   = (tid & 1) * 8;
    const float* gA = Wvr + (long long)(m0 + arow) * CC + ac;
    // B staging: thread t -> k-row t>>4 (0..15), n-col (t&15)*8
    const int bk = tid >> 4;
    const int bn = (tid & 15) * 8;
    const float* gB = xb + (long long)bk * NN + n0 + bn;

    const uint32_t sbase = smem_u32(sm);
    const uint32_t sA_st = sbase + (uint32_t)(arow * OSTR + ac) * 4u;
    const uint32_t sB_st = sbase + (uint32_t)(VATILE + bk * VBSTR + bn) * 4u;

#define VX_ISSUE(c)                                                        \
    do {                                                                   \
        const uint32_t off_ = (uint32_t)((c) & 3) * (VSTAGE * 4u);         \
        const float* pa_ = gA + (c) * 16;                                  \
        const float* pb_ = gB + (long long)(c) * 16 * NN;                  \
        cp_async16(sA_st + off_,      pa_);                                \
        cp_async16(sA_st + off_ + 16, pa_ + 4);                            \
        cp_async16(sB_st + off_,      pb_);                                \
        cp_async16(sB_st + off_ + 16, pb_ + 4);                            \
        cp_commit();                                                       \
    } while (0)

    VX_ISSUE(0); VX_ISSUE(1); VX_ISSUE(2);

    const int wid  = tid >> 5, lane = tid & 31;
    const int wm   = (wid >> 2) * 64;
    const int wn   = (wid & 3) * 32;
    const int g4   = lane >> 2;
    const int tg   = lane & 3;

    float acc[4][4][4];
    #pragma unroll
    for (int i = 0; i < 4; i++)
        #pragma unroll
        for (int j = 0; j < 4; j++)
            #pragma unroll
            for (int r = 0; r < 4; r++) acc[i][j][r] = 0.f;

    for (int c = 0; c < VNCH; c++) {
        if (c + 2 < VNCH)       cp_wait<2>();
        else if (c + 1 < VNCH)  cp_wait<1>();
        else                    cp_wait<0>();
        __syncthreads();

        if (c + 3 < VNCH) VX_ISSUE(c + 3);

        const float* A_ = sm + (c & 3) * VSTAGE;
        const float* B_ = A_ + VATILE;

        #pragma unroll
        for (int s = 0; s < 2; s++) {
            const int kk = s * 8 + tg;
            uint32_t a[4][4], b[4][2];
            #pragma unroll
            for (int mt = 0; mt < 4; mt++) {
                const int r0 = wm + mt * 16 + g4;
                a[mt][0] = __float_as_uint(A_[r0 * OSTR + kk]);
                a[mt][1] = __float_as_uint(A_[(r0 + 8) * OSTR + kk]);
                a[mt][2] = __float_as_uint(A_[r0 * OSTR + kk + 4]);
                a[mt][3] = __float_as_uint(A_[(r0 + 8) * OSTR + kk + 4]);
            }
            #pragma unroll
            for (int nt = 0; nt < 4; nt++) {
                const int nr = wn + nt * 8 + g4;
                b[nt][0] = f2tf32(B_[kk * VBSTR + nr]);
                b[nt][1] = f2tf32(B_[(kk + 4) * VBSTR + nr]);
            }
            #pragma unroll
            for (int mt = 0; mt < 4; mt++)
                #pragma unroll
                for (int nt = 0; nt < 4; nt++)
                    mma16888(acc[mt][nt], a[mt], b[nt]);
        }
    }

    // epilogue: store v tf32-rounded (consumed by ov_mma_kernel without cvt)
    #pragma unroll
    for (int mt = 0; mt < 4; mt++) {
        #pragma unroll
        for (int half = 0; half < 2; half++) {
            const int m = m0 + wm + mt * 16 + g4 + half * 8;
            const long long rb = (long long)m * NN;
            #pragma unroll
            for (int nt = 0; nt < 4; nt++) {
                const int n = n0 + wn + nt * 8 + 2 * tg;
                float2 o;
                o.x = __uint_as_float(f2tf32(acc[mt][nt][half * 2 + 0]));
                o.y = __uint_as_float(f2tf32(acc[mt][nt][half * 2 + 1]));
                *(float2*)(Vb + rb + n) = o;
            }
        }
    }
#undef VX_ISSUE
}

// ---------------- generic tiled SGEMM (fp32 SIMT, logit path) ----------------
static const int TM = 128, TN = 128, TK = 16;

template<bool AK, bool BK, bool EPI>
__global__ __launch_bounds__(256, 2)
void gemm_k(const float* __restrict__ A, const float* __restrict__ Bm,
            float* __restrict__ Cm, int M, int N, int K,
            long long sA, long long sB, long long sC,
            const float* __restrict__ R, long long sR,
            const float* __restrict__ gamma_p)
{
    A  += sA * (long long)blockIdx.z;
    Bm += sB * (long long)blockIdx.z;
    Cm += sC * (long long)blockIdx.z;
    if (EPI) R += sR * (long long)blockIdx.z;

    __shared__ float As[TK][TM];
    __shared__ float Bs[TK][TN];

    const int tid = threadIdx.x;
    const int n0 = blockIdx.x * TN;
    const int m0 = blockIdx.y * TM;
    const int tx = tid & 15;
    const int ty = tid >> 4;

    float acc[8][8];
    #pragma unroll
    for (int i = 0; i < 8; i++)
        #pragma unroll
        for (int j = 0; j < 8; j++) acc[i][j] = 0.f;

    for (int k0 = 0; k0 < K; k0 += TK) {
        if (AK) {
            const int row = tid >> 1;
            const int kc  = (tid & 1) * 8;
            const int m   = m0 + row;
            float4 v0 = make_float4(0.f, 0.f, 0.f, 0.f), v1 = v0;
            if (m < M) {
                const float* p = A + (long long)m * K + k0 + kc;
                v0 = *(const float4*)p;
                v1 = *(const float4*)(p + 4);
            }
            As[kc + 0][row] = v0.x; As[kc + 1][row] = v0.y;
            As[kc + 2][row] = v0.z; As[kc + 3][row] = v0.w;
            As[kc + 4][row] = v1.x; As[kc + 5][row] = v1.y;
            As[kc + 6][row] = v1.z; As[kc + 7][row] = v1.w;
        } else {
            const int kr = tid >> 4;
            const int mc = (tid & 15) * 8;
            const float* p = A + (long long)(k0 + kr) * M + m0 + mc;
            *(float4*)&As[kr][mc]     = *(const float4*)p;
            *(float4*)&As[kr][mc + 4] = *(const float4*)(p + 4);
        }
        if (!BK) {
            const int kr = tid >> 4;
            const int nc = (tid & 15) * 8;
            const float* p = Bm + (long long)(k0 + kr) * N + n0 + nc;
            *(float4*)&Bs[kr][nc]     = *(const float4*)p;
            *(float4*)&Bs[kr][nc + 4] = *(const float4*)(p + 4);
        } else {
            const int row = tid >> 1;
            const int kc  = (tid & 1) * 8;
            const float* p = Bm + (long long)(n0 + row) * K + k0 + kc;
            float4 v0 = *(const float4*)p;
            float4 v1 = *(const float4*)(p + 4);
            Bs[kc + 0][row] = v0.x; Bs[kc + 1][row] = v0.y;
            Bs[kc + 2][row] = v0.z; Bs[kc + 3][row] = v0.w;
            Bs[kc + 4][row] = v1.x; Bs[kc + 5][row] = v1.y;
            Bs[kc + 6][row] = v1.z; Bs[kc + 7][row] = v1.w;
        }
        __syncthreads();

        #pragma unroll
        for (int kk = 0; kk < TK; kk++) {
            float a[8], b[8];
            *(float4*)(a)     = *(const float4*)&As[kk][ty * 8];
            *(float4*)(a + 4) = *(const float4*)&As[kk][ty * 8 + 4];
            *(float4*)(b)     = *(const float4*)&Bs[kk][tx * 8];
            *(float4*)(b + 4) = *(const float4*)&Bs[kk][tx * 8 + 4];
            #pragma unroll
            for (int i = 0; i < 8; i++)
                #pragma unroll
                for (int j = 0; j < 8; j++)
                    acc[i][j] = fmaf(a[i], b[j], acc[i][j]);
        }
        __syncthreads();
    }

    const float g = EPI ? *gamma_p : 0.f;
    #pragma unroll
    for (int i = 0; i < 8; i++) {
        const int m = m0 + ty * 8 + i;
        if (m < M) {
            float* dst = Cm + (long long)m * N + n0 + tx * 8;
            if (EPI) {
                const float* r = R + (long long)m * N + n0 + tx * 8;
                float4 r0 = *(const float4*)r;
                float4 r1 = *(const float4*)(r + 4);
                float4 o0, o1;
                o0.x = fmaf(g, acc[i][0], r0.x); o0.y = fmaf(g, acc[i][1], r0.y);
                o0.z = fmaf(g, acc[i][2], r0.z); o0.w = fmaf(g, acc[i][3], r0.w);
                o1.x = fmaf(g, acc[i][4], r1.x); o1.y = fmaf(g, acc[i][5], r1.y);
                o1.z = fmaf(g, acc[i][6], r1.z); o1.w = fmaf(g, acc[i][7], r1.w);
                *(float4*)dst       = o0;
                *(float4*)(dst + 4) = o1;
            } else {
                float4 o0 = make_float4(acc[i][0], acc[i][1], acc[i][2], acc[i][3]);
                float4 o1 = make_float4(acc[i][4], acc[i][5], acc[i][6], acc[i][7]);
                *(float4*)dst       = o0;
                *(float4*)(dst + 4) = o1;
            }
        }
    }
}

// ---------------- row softmax over 2304 columns; stores tf32-rounded P ----------------
__global__ __launch_bounds__(256)
void softmax_rows(float* __restrict__ S)
{
    __shared__ float red[8];
    float* p = S + (size_t)blockIdx.x * NN;
    const int tid  = threadIdx.x;
    const int lane = tid & 31;
    const int wid  = tid >> 5;

    float v[9];
    float m = -1e30f;
    #pragma unroll
    for (int j = 0; j < 9; j++) {
        v[j] = p[tid + 256 * j];
        m = fmaxf(m, v[j]);
    }
    #pragma unroll
    for (int o = 16; o; o >>= 1) m = fmaxf(m, __shfl_xor_sync(0xffffffffu, m, o));
    if (lane == 0) red[wid] = m;
    __syncthreads();
    m = red[0];
    #pragma unroll
    for (int i = 1; i < 8; i++) m = fmaxf(m, red[i]);
    __syncthreads();

    float s = 0.f;
    #pragma unroll
    for (int j = 0; j < 9; j++) {
        v[j] = expf(v[j] - m);
        s += v[j];
    }
    #pragma unroll
    for (int o = 16; o; o >>= 1) s += __shfl_xor_sync(0xffffffffu, s, o);
    if (lane == 0) red[wid] = s;
    __syncthreads();
    s = 0.f;
    #pragma unroll
    for (int i = 0; i < 8; i++) s += red[i];

    const float inv = 1.f / s;
    #pragma unroll
    for (int j = 0; j < 9; j++)
        p[tid + 256 * j] = __uint_as_float(f2tf32(v[j] * inv));
}

// ---------------- launch ----------------
extern "C" void kernel_launch(void* const* d_in, const int* in_sizes, int n_in,
                              void* d_out, int out_size)
{
    const float* x     = (const float*)d_in[0];   // (16,512,48,48)
    const float* Wq    = (const float*)d_in[1];   // (64,512)
    const float* Wk    = (const float*)d_in[2];   // (64,512)
    const float* Wv    = (const float*)d_in[3];   // (512,512)
    const float* gamma = (const float*)d_in[4];   // (1,)
    float* out = (float*)d_out;

    float *qk, *v, *s, *wqk, *wvr;
    cudaGetSymbolAddress((void**)&qk,  g_qk);
    cudaGetSymbolAddress((void**)&v,   g_v);
    cudaGetSymbolAddress((void**)&s,   g_s);
    cudaGetSymbolAddress((void**)&wqk, g_wqk);
    cudaGetSymbolAddress((void**)&wvr, g_wvr);

    const long long sX  = (long long)CC * NN;
    const long long sQK = (long long)128 * NN;
    const long long sS  = (long long)NN * NN;

    dim3 blk(256);

    // 0. prep: concat [Wq;Wk], round Wv
    prep_kernel<<<(CC * CC + 255) / 256, 256>>>(Wq, Wk, Wv);

    // 1. [q; k] = [Wq; Wk] @ x : M=128, N=2304, K=512 (fp32 SIMT, one launch)
    gemm_k<true, false, false><<<dim3(NN / TN, 1, BB), blk>>>(
        wqk, x, qk, 128, NN, CC, 0, sX, sQK, nullptr, 0, nullptr);

    // 2. v = Wv @ x : tf32 mma (output tf32-rounded)
    cudaFuncSetAttribute(vx_mma_kernel,
                         cudaFuncAttributeMaxDynamicSharedMemorySize, VX_SMEM);
    vx_mma_kernel<<<dim3(NN / 128, CC / 128, BB), blk, VX_SMEM>>>(wvr, x, v);

    // 3. S = q^T @ k : fp32 SIMT (logits must stay accurate)
    gemm_k<false, false, false><<<dim3(NN / TN, NN / TM, BB), blk>>>(
        qk, qk + (long long)II * NN, s, NN, NN, II, sQK, sQK, sS,
        nullptr, 0, nullptr);

    // 4. P = softmax_rows(S) in place (output tf32-rounded)
    softmax_rows<<<BB * NN, 256>>>(s);

    // 5. out = gamma * (v @ P^T) + x : tf32 mma, no cvt in inner loop
    cudaFuncSetAttribute(ov_mma_kernel,
                         cudaFuncAttributeMaxDynamicSharedMemorySize, OV_SMEM);
    ov_mma_kernel<<<dim3(NN / 128, CC / 128, BB), blk, OV_SMEM>>>(
        v, s, x, out, gamma);
}

// round 8
// speedup vs baseline: 1.4127x; 1.4127x over previous
#include <cuda_runtime.h>
#include <stdint.h>
#include <math.h>

// Problem constants
#define BB 16
#define CC 512
#define NN 2304      // 48*48
#define II 64

// ---------------- scratch (static device globals; no allocation) ----------------
__device__ float g_q[(size_t)BB * II * NN];          //  9 MB
__device__ float g_k[(size_t)BB * II * NN];          //  9 MB
__device__ float g_v[(size_t)BB * CC * NN];          // 72 MB
__device__ float g_s[(size_t)BB * NN * NN];          // 324 MB (S, then P in place)

// =====================================================================
// helpers
// =====================================================================
__device__ __forceinline__ uint32_t smem_u32(const void* p) {
    uint32_t a;
    asm("{ .reg .u64 t; cvta.to.shared.u64 t, %1; cvt.u32.u64 %0, t; }"
        : "=r"(a) : "l"(p));
    return a;
}

__device__ __forceinline__ void cp_async16(uint32_t saddr, const void* gptr) {
    asm volatile("cp.async.cg.shared.global [%0], [%1], 16;"
                 :: "r"(saddr), "l"(gptr) : "memory");
}
__device__ __forceinline__ void cp_commit() {
    asm volatile("cp.async.commit_group;" ::: "memory");
}
template<int N>
__device__ __forceinline__ void cp_wait() {
    asm volatile("cp.async.wait_group %0;" :: "n"(N) : "memory");
}

__device__ __forceinline__ uint32_t f2tf32(float f) {
    uint32_t u;
    asm("cvt.rna.tf32.f32 %0, %1;" : "=r"(u) : "f"(f));
    return u;
}

// D += A(16x8, row) * B(8x8, col); fp32 accumulate, tf32 operands
__device__ __forceinline__ void mma16888(float* d, const uint32_t* a, const uint32_t* b) {
    asm volatile(
        "mma.sync.aligned.m16n8k8.row.col.f32.tf32.tf32.f32 "
        "{%0,%1,%2,%3}, {%4,%5,%6,%7}, {%8,%9}, {%0,%1,%2,%3};"
        : "+f"(d[0]), "+f"(d[1]), "+f"(d[2]), "+f"(d[3])
        : "r"(a[0]), "r"(a[1]), "r"(a[2]), "r"(a[3]), "r"(b[0]), "r"(b[1]));
}

// =====================================================================
// O = gamma * (V @ P^T) + X via mma.sync tf32   (EXACTLY as round 4)
// C[m,n] = sum_k V[m,k] * P[n,k]; both operands K-contiguous (NT / row.col)
// CTA tile 128x128, K chunks of 16, 4-stage cp.async ring.
// =====================================================================
#define OSTR 20                     // smem row stride (floats), conflict-free frags
#define OTILE (128 * OSTR)          // floats per operand tile
#define OSTAGE (2 * OTILE)          // A + B per stage
#define ONCH (NN / 16)              // 144 k-chunks
#define OV_SMEM (4 * OSTAGE * 4)    // bytes: 81920

__global__ __launch_bounds__(256, 2)
void ov_mma_kernel(const float* __restrict__ V, const float* __restrict__ P,
                   const float* __restrict__ X, float* __restrict__ O,
                   const float* __restrict__ gamma_p)
{
    extern __shared__ float sm[];

    const int tid = threadIdx.x;
    const long long bz = blockIdx.z;
    const float* Vb = V + bz * (long long)(CC * NN);
    const float* Pb = P + bz * (long long)(NN * NN);
    const float* Xb = X + bz * (long long)(CC * NN);
    float*       Ob = O + bz * (long long)(CC * NN);

    const int m0 = blockIdx.y * 128;
    const int n0 = blockIdx.x * 128;

    const int lrow = tid >> 1;
    const int lc   = (tid & 1) * 8;
    const float* gA = Vb + (long long)(m0 + lrow) * NN + lc;
    const float* gB = Pb + (long long)(n0 + lrow) * NN + lc;
    const uint32_t sbase = smem_u32(sm);
    const uint32_t sA_st = sbase + (uint32_t)(lrow * OSTR + lc) * 4u;
    const uint32_t sB_st = sA_st + OTILE * 4u;

#define OV_ISSUE(c)                                                        \
    do {                                                                   \
        const uint32_t off_ = (uint32_t)((c) & 3) * (OSTAGE * 4u);         \
        const float* pa_ = gA + (c) * 16;                                  \
        const float* pb_ = gB + (c) * 16;                                  \
        cp_async16(sA_st + off_,      pa_);                                \
        cp_async16(sA_st + off_ + 16, pa_ + 4);                            \
        cp_async16(sB_st + off_,      pb_);                                \
        cp_async16(sB_st + off_ + 16, pb_ + 4);                            \
        cp_commit();                                                       \
    } while (0)

    OV_ISSUE(0); OV_ISSUE(1); OV_ISSUE(2);

    const int wid  = tid >> 5, lane = tid & 31;
    const int wm   = (wid >> 2) * 64;    // warp m offset (2 rows of warps)
    const int wn   = (wid & 3) * 32;     // warp n offset (4 cols of warps)
    const int g4   = lane >> 2;          // groupID 0..7
    const int tg   = lane & 3;           // thread-in-group 0..3

    float acc[4][4][4];
    #pragma unroll
    for (int i = 0; i < 4; i++)
        #pragma unroll
        for (int j = 0; j < 4; j++)
            #pragma unroll
            for (int r = 0; r < 4; r++) acc[i][j][r] = 0.f;

    for (int c = 0; c < ONCH; c++) {
        if (c + 2 < ONCH)       cp_wait<2>();
        else if (c + 1 < ONCH)  cp_wait<1>();
        else                    cp_wait<0>();
        __syncthreads();

        if (c + 3 < ONCH) OV_ISSUE(c + 3);

        const float* A_ = sm + (c & 3) * OSTAGE;
        const float* B_ = A_ + OTILE;

        #pragma unroll
        for (int s = 0; s < 2; s++) {
            const int kk = s * 8 + tg;
            uint32_t a[4][4], b[4][2];
            #pragma unroll
            for (int mt = 0; mt < 4; mt++) {
                const int r0 = wm + mt * 16 + g4;
                a[mt][0] = f2tf32(A_[r0 * OSTR + kk]);
                a[mt][1] = f2tf32(A_[(r0 + 8) * OSTR + kk]);
                a[mt][2] = f2tf32(A_[r0 * OSTR + kk + 4]);
                a[mt][3] = f2tf32(A_[(r0 + 8) * OSTR + kk + 4]);
            }
            #pragma unroll
            for (int nt = 0; nt < 4; nt++) {
                const int nr = wn + nt * 8 + g4;
                b[nt][0] = f2tf32(B_[nr * OSTR + kk]);
                b[nt][1] = f2tf32(B_[nr * OSTR + kk + 4]);
            }
            #pragma unroll
            for (int mt = 0; mt < 4; mt++)
                #pragma unroll
                for (int nt = 0; nt < 4; nt++)
                    mma16888(acc[mt][nt], a[mt], b[nt]);
        }
    }

    const float g = *gamma_p;
    #pragma unroll
    for (int mt = 0; mt < 4; mt++) {
        #pragma unroll
        for (int half = 0; half < 2; half++) {
            const int m = m0 + wm + mt * 16 + g4 + half * 8;
            const long long rb = (long long)m * NN;
            #pragma unroll
            for (int nt = 0; nt < 4; nt++) {
                const int n = n0 + wn + nt * 8 + 2 * tg;
                float2 xr = *(const float2*)(Xb + rb + n);
                float2 o;
                o.x = fmaf(g, acc[mt][nt][half * 2 + 0], xr.x);
                o.y = fmaf(g, acc[mt][nt][half * 2 + 1], xr.y);
                *(float2*)(Ob + rb + n) = o;
            }
        }
    }
#undef OV_ISSUE
}

// =====================================================================
// NEW (sole change this round): v = Wv @ x via mma.sync tf32
// C[c,n] = sum_k Wv[c,k] * x[k,n]. A (Wv) K-contiguous, staged [m][k];
// B (x) stored (K,N): staged [k][n] with row stride 136 (conflict-free).
// cvt.rna on both fragment paths at load; stores plain fp32.
// =====================================================================
#define VBSTR 136                    // B smem row stride (floats): 8*tg+g4 distinct
#define VATILE (128 * OSTR)          // 2560 floats
#define VBTILE (16 * VBSTR)          // 2176 floats
#define VSTAGE (VATILE + VBTILE)     // 4736 floats
#define VNCH (CC / 16)               // 32 k-chunks
#define VX_SMEM (4 * VSTAGE * 4)     // 75776 bytes

__global__ __launch_bounds__(256, 2)
void vx_mma_kernel(const float* __restrict__ Wv, const float* __restrict__ x,
                   float* __restrict__ Vout)
{
    extern __shared__ float sm[];

    const int tid = threadIdx.x;
    const long long bz = blockIdx.z;
    const float* xb = x + bz * (long long)(CC * NN);
    float*       Vb = Vout + bz * (long long)(CC * NN);

    const int m0 = blockIdx.y * 128;
    const int n0 = blockIdx.x * 128;

    // A staging: thread t -> row t>>1, 8-float half (t&1)*8
    const int arow = tid >> 1;
    const int ac   = (tid & 1) * 8;
    const float* gA = Wv + (long long)(m0 + arow) * CC + ac;
    // B staging: thread t -> k-row t>>4 (0..15), n-col (t&15)*8
    const int bk = tid >> 4;
    const int bn = (tid & 15) * 8;
    const float* gB = xb + (long long)bk * NN + n0 + bn;

    const uint32_t sbase = smem_u32(sm);
    const uint32_t sA_st = sbase + (uint32_t)(arow * OSTR + ac) * 4u;
    const uint32_t sB_st = sbase + (uint32_t)(VATILE + bk * VBSTR + bn) * 4u;

#define VX_ISSUE(c)                                                        \
    do {                                                                   \
        const uint32_t off_ = (uint32_t)((c) & 3) * (VSTAGE * 4u);         \
        const float* pa_ = gA + (c) * 16;                                  \
        const float* pb_ = gB + (long long)(c) * 16 * NN;                  \
        cp_async16(sA_st + off_,      pa_);                                \
        cp_async16(sA_st + off_ + 16, pa_ + 4);                            \
        cp_async16(sB_st + off_,      pb_);                                \
        cp_async16(sB_st + off_ + 16, pb_ + 4);                            \
        cp_commit();                                                       \
    } while (0)

    VX_ISSUE(0); VX_ISSUE(1); VX_ISSUE(2);

    const int wid  = tid >> 5, lane = tid & 31;
    const int wm   = (wid >> 2) * 64;
    const int wn   = (wid & 3) * 32;
    const int g4   = lane >> 2;
    const int tg   = lane & 3;

    float acc[4][4][4];
    #pragma unroll
    for (int i = 0; i < 4; i++)
        #pragma unroll
        for (int j = 0; j < 4; j++)
            #pragma unroll
            for (int r = 0; r < 4; r++) acc[i][j][r] = 0.f;

    for (int c = 0; c < VNCH; c++) {
        if (c + 2 < VNCH)       cp_wait<2>();
        else if (c + 1 < VNCH)  cp_wait<1>();
        else                    cp_wait<0>();
        __syncthreads();

        if (c + 3 < VNCH) VX_ISSUE(c + 3);

        const float* A_ = sm + (c & 3) * VSTAGE;
        const float* B_ = A_ + VATILE;

        #pragma unroll
        for (int s = 0; s < 2; s++) {
            const int kk = s * 8 + tg;
            uint32_t a[4][4], b[4][2];
            #pragma unroll
            for (int mt = 0; mt < 4; mt++) {
                const int r0 = wm + mt * 16 + g4;
                a[mt][0] = f2tf32(A_[r0 * OSTR + kk]);
                a[mt][1] = f2tf32(A_[(r0 + 8) * OSTR + kk]);
                a[mt][2] = f2tf32(A_[r0 * OSTR + kk + 4]);
                a[mt][3] = f2tf32(A_[(r0 + 8) * OSTR + kk + 4]);
            }
            #pragma unroll
            for (int nt = 0; nt < 4; nt++) {
                const int nr = wn + nt * 8 + g4;
                b[nt][0] = f2tf32(B_[kk * VBSTR + nr]);
                b[nt][1] = f2tf32(B_[(kk + 4) * VBSTR + nr]);
            }
            #pragma unroll
            for (int mt = 0; mt < 4; mt++)
                #pragma unroll
                for (int nt = 0; nt < 4; nt++)
                    mma16888(acc[mt][nt], a[mt], b[nt]);
        }
    }

    #pragma unroll
    for (int mt = 0; mt < 4; mt++) {
        #pragma unroll
        for (int half = 0; half < 2; half++) {
            const int m = m0 + wm + mt * 16 + g4 + half * 8;
            const long long rb = (long long)m * NN;
            #pragma unroll
            for (int nt = 0; nt < 4; nt++) {
                const int n = n0 + wn + nt * 8 + 2 * tg;
                float2 o;
                o.x = acc[mt][nt][half * 2 + 0];
                o.y = acc[mt][nt][half * 2 + 1];
                *(float2*)(Vb + rb + n) = o;
            }
        }
    }
#undef VX_ISSUE
}

// ---------------- generic tiled SGEMM (fp32 SIMT, logit path) ----------------
static const int TM = 128, TN = 128, TK = 16;

template<bool AK, bool BK, bool EPI>
__global__ __launch_bounds__(256, 2)
void gemm_k(const float* __restrict__ A, const float* __restrict__ Bm,
            float* __restrict__ Cm, int M, int N, int K,
            long long sA, long long sB, long long sC,
            const float* __restrict__ R, long long sR,
            const float* __restrict__ gamma_p)
{
    A  += sA * (long long)blockIdx.z;
    Bm += sB * (long long)blockIdx.z;
    Cm += sC * (long long)blockIdx.z;
    if (EPI) R += sR * (long long)blockIdx.z;

    __shared__ float As[TK][TM];
    __shared__ float Bs[TK][TN];

    const int tid = threadIdx.x;
    const int n0 = blockIdx.x * TN;
    const int m0 = blockIdx.y * TM;
    const int tx = tid & 15;
    const int ty = tid >> 4;

    float acc[8][8];
    #pragma unroll
    for (int i = 0; i < 8; i++)
        #pragma unroll
        for (int j = 0; j < 8; j++) acc[i][j] = 0.f;

    for (int k0 = 0; k0 < K; k0 += TK) {
        if (AK) {
            const int row = tid >> 1;
            const int kc  = (tid & 1) * 8;
            const int m   = m0 + row;
            float4 v0 = make_float4(0.f, 0.f, 0.f, 0.f), v1 = v0;
            if (m < M) {
                const float* p = A + (long long)m * K + k0 + kc;
                v0 = *(const float4*)p;
                v1 = *(const float4*)(p + 4);
            }
            As[kc + 0][row] = v0.x; As[kc + 1][row] = v0.y;
            As[kc + 2][row] = v0.z; As[kc + 3][row] = v0.w;
            As[kc + 4][row] = v1.x; As[kc + 5][row] = v1.y;
            As[kc + 6][row] = v1.z; As[kc + 7][row] = v1.w;
        } else {
            const int kr = tid >> 4;
            const int mc = (tid & 15) * 8;
            const float* p = A + (long long)(k0 + kr) * M + m0 + mc;
            *(float4*)&As[kr][mc]     = *(const float4*)p;
            *(float4*)&As[kr][mc + 4] = *(const float4*)(p + 4);
        }
        if (!BK) {
            const int kr = tid >> 4;
            const int nc = (tid & 15) * 8;
            const float* p = Bm + (long long)(k0 + kr) * N + n0 + nc;
            *(float4*)&Bs[kr][nc]     = *(const float4*)p;
            *(float4*)&Bs[kr][nc + 4] = *(const float4*)(p + 4);
        } else {
            const int row = tid >> 1;
            const int kc  = (tid & 1) * 8;
            const float* p = Bm + (long long)(n0 + row) * K + k0 + kc;
            float4 v0 = *(const float4*)p;
            float4 v1 = *(const float4*)(p + 4);
            Bs[kc + 0][row] = v0.x; Bs[kc + 1][row] = v0.y;
            Bs[kc + 2][row] = v0.z; Bs[kc + 3][row] = v0.w;
            Bs[kc + 4][row] = v1.x; Bs[kc + 5][row] = v1.y;
            Bs[kc + 6][row] = v1.z; Bs[kc + 7][row] = v1.w;
        }
        __syncthreads();

        #pragma unroll
        for (int kk = 0; kk < TK; kk++) {
            float a[8], b[8];
            *(float4*)(a)     = *(const float4*)&As[kk][ty * 8];
            *(float4*)(a + 4) = *(const float4*)&As[kk][ty * 8 + 4];
            *(float4*)(b)     = *(const float4*)&Bs[kk][tx * 8];
            *(float4*)(b + 4) = *(const float4*)&Bs[kk][tx * 8 + 4];
            #pragma unroll
            for (int i = 0; i < 8; i++)
                #pragma unroll
                for (int j = 0; j < 8; j++)
                    acc[i][j] = fmaf(a[i], b[j], acc[i][j]);
        }
        __syncthreads();
    }

    const float g = EPI ? *gamma_p : 0.f;
    #pragma unroll
    for (int i = 0; i < 8; i++) {
        const int m = m0 + ty * 8 + i;
        if (m < M) {
            float* dst = Cm + (long long)m * N + n0 + tx * 8;
            if (EPI) {
                const float* r = R + (long long)m * N + n0 + tx * 8;
                float4 r0 = *(const float4*)r;
                float4 r1 = *(const float4*)(r + 4);
                float4 o0, o1;
                o0.x = fmaf(g, acc[i][0], r0.x); o0.y = fmaf(g, acc[i][1], r0.y);
                o0.z = fmaf(g, acc[i][2], r0.z); o0.w = fmaf(g, acc[i][3], r0.w);
                o1.x = fmaf(g, acc[i][4], r1.x); o1.y = fmaf(g, acc[i][5], r1.y);
                o1.z = fmaf(g, acc[i][6], r1.z); o1.w = fmaf(g, acc[i][7], r1.w);
                *(float4*)dst       = o0;
                *(float4*)(dst + 4) = o1;
            } else {
                float4 o0 = make_float4(acc[i][0], acc[i][1], acc[i][2], acc[i][3]);
                float4 o1 = make_float4(acc[i][4], acc[i][5], acc[i][6], acc[i][7]);
                *(float4*)dst       = o0;
                *(float4*)(dst + 4) = o1;
            }
        }
    }
}

// ---------------- row softmax over 2304 columns, in place ----------------
__global__ __launch_bounds__(256)
void softmax_rows(float* __restrict__ S)
{
    __shared__ float red[8];
    float* p = S + (size_t)blockIdx.x * NN;
    const int tid  = threadIdx.x;
    const int lane = tid & 31;
    const int wid  = tid >> 5;

    float v[9];
    float m = -1e30f;
    #pragma unroll
    for (int j = 0; j < 9; j++) {
        v[j] = p[tid + 256 * j];
        m = fmaxf(m, v[j]);
    }
    #pragma unroll
    for (int o = 16; o; o >>= 1) m = fmaxf(m, __shfl_xor_sync(0xffffffffu, m, o));
    if (lane == 0) red[wid] = m;
    __syncthreads();
    m = red[0];
    #pragma unroll
    for (int i = 1; i < 8; i++) m = fmaxf(m, red[i]);
    __syncthreads();

    float s = 0.f;
    #pragma unroll
    for (int j = 0; j < 9; j++) {
        v[j] = expf(v[j] - m);
        s += v[j];
    }
    #pragma unroll
    for (int o = 16; o; o >>= 1) s += __shfl_xor_sync(0xffffffffu, s, o);
    if (lane == 0) red[wid] = s;
    __syncthreads();
    s = 0.f;
    #pragma unroll
    for (int i = 0; i < 8; i++) s += red[i];

    const float inv = 1.f / s;
    #pragma unroll
    for (int j = 0; j < 9; j++) p[tid + 256 * j] = v[j] * inv;
}

// ---------------- launch ----------------
extern "C" void kernel_launch(void* const* d_in, const int* in_sizes, int n_in,
                              void* d_out, int out_size)
{
    const float* x     = (const float*)d_in[0];   // (16,512,48,48)
    const float* Wq    = (const float*)d_in[1];   // (64,512)
    const float* Wk    = (const float*)d_in[2];   // (64,512)
    const float* Wv    = (const float*)d_in[3];   // (512,512)
    const float* gamma = (const float*)d_in[4];   // (1,)
    float* out = (float*)d_out;

    float *q, *k, *v, *s;
    cudaGetSymbolAddress((void**)&q, g_q);
    cudaGetSymbolAddress((void**)&k, g_k);
    cudaGetSymbolAddress((void**)&v, g_v);
    cudaGetSymbolAddress((void**)&s, g_s);

    const long long sX = (long long)CC * NN;
    const long long sQ = (long long)II * NN;
    const long long sS = (long long)NN * NN;

    dim3 blk(256);

    // q = Wq @ x, k = Wk @ x  (fp32 SIMT, as round 4)
    gemm_k<true, false, false><<<dim3(NN / TN, 1, BB), blk>>>(
        Wq, x, q, II, NN, CC, 0, sX, sQ, nullptr, 0, nullptr);
    gemm_k<true, false, false><<<dim3(NN / TN, 1, BB), blk>>>(
        Wk, x, k, II, NN, CC, 0, sX, sQ, nullptr, 0, nullptr);

    // v = Wv @ x  — SOLE CHANGE: tf32 mma instead of SIMT
    cudaFuncSetAttribute(vx_mma_kernel,
                         cudaFuncAttributeMaxDynamicSharedMemorySize, VX_SMEM);
    vx_mma_kernel<<<dim3(NN / 128, CC / 128, BB), blk, VX_SMEM>>>(Wv, x, v);

    // S = q^T @ k  (fp32 SIMT — logits must stay accurate)
    gemm_k<false, false, false><<<dim3(NN / TN, NN / TM, BB), blk>>>(
        q, k, s, NN, NN, II, sQ, sQ, sS, nullptr, 0, nullptr);

    // P = softmax_rows(S) in place (plain fp32, as round 4)
    softmax_rows<<<BB * NN, 256>>>(s);

    // out = gamma * (v @ P^T) + x  — tf32 mma (exact round-4 kernel)
    cudaFuncSetAttribute(ov_mma_kernel,
                         cudaFuncAttributeMaxDynamicSharedMemorySize, OV_SMEM);
    ov_mma_kernel<<<dim3(NN / 128, CC / 128, BB), blk, OV_SMEM>>>(
        v, s, x, out, gamma);
}

// round 9
// speedup vs baseline: 1.8897x; 1.3376x over previous
#include <cuda_runtime.h>
#include <cuda_fp16.h>
#include <stdint.h>
#include <math.h>

// Problem constants
#define BB 16
#define CC 512
#define NN 2304      // 48*48
#define II 64

// ---------------- scratch (static device globals; no allocation) ----------------
__device__ float  g_q[(size_t)BB * II * NN];          //   9 MB
__device__ float  g_k[(size_t)BB * II * NN];          //   9 MB
__device__ float  g_s[(size_t)BB * NN * NN];          // 324 MB (fp32 logits S)
__device__ __half g_ph[(size_t)BB * NN * NN];         // 162 MB (fp16 softmax P)
__device__ __half g_vh[(size_t)BB * CC * NN];         //  36 MB (fp16 V)

// =====================================================================
// helpers
// =====================================================================
__device__ __forceinline__ uint32_t smem_u32(const void* p) {
    uint32_t a;
    asm("{ .reg .u64 t; cvta.to.shared.u64 t, %1; cvt.u32.u64 %0, t; }"
        : "=r"(a) : "l"(p));
    return a;
}

__device__ __forceinline__ void cp_async16(uint32_t saddr, const void* gptr) {
    asm volatile("cp.async.cg.shared.global [%0], [%1], 16;"
                 :: "r"(saddr), "l"(gptr) : "memory");
}
__device__ __forceinline__ void cp_commit() {
    asm volatile("cp.async.commit_group;" ::: "memory");
}
template<int N>
__device__ __forceinline__ void cp_wait() {
    asm volatile("cp.async.wait_group %0;" :: "n"(N) : "memory");
}

__device__ __forceinline__ uint32_t f2tf32(float f) {
    uint32_t u;
    asm("cvt.rna.tf32.f32 %0, %1;" : "=r"(u) : "f"(f));
    return u;
}

// tf32: D += A(16x8) * B(8x8)
__device__ __forceinline__ void mma16888(float* d, const uint32_t* a, const uint32_t* b) {
    asm volatile(
        "mma.sync.aligned.m16n8k8.row.col.f32.tf32.tf32.f32 "
        "{%0,%1,%2,%3}, {%4,%5,%6,%7}, {%8,%9}, {%0,%1,%2,%3};"
        : "+f"(d[0]), "+f"(d[1]), "+f"(d[2]), "+f"(d[3])
        : "r"(a[0]), "r"(a[1]), "r"(a[2]), "r"(a[3]), "r"(b[0]), "r"(b[1]));
}

// fp16: D += A(16x16) * B(16x8), fp32 accumulate
__device__ __forceinline__ void mma168816(float* d, const uint32_t* a, const uint32_t* b) {
    asm volatile(
        "mma.sync.aligned.m16n8k16.row.col.f32.f16.f16.f32 "
        "{%0,%1,%2,%3}, {%4,%5,%6,%7}, {%8,%9}, {%0,%1,%2,%3};"
        : "+f"(d[0]), "+f"(d[1]), "+f"(d[2]), "+f"(d[3])
        : "r"(a[0]), "r"(a[1]), "r"(a[2]), "r"(a[3]), "r"(b[0]), "r"(b[1]));
}

// =====================================================================
// O = gamma * (V @ P^T) + X via fp16 mma.sync (fp32 accumulate)
// V, P pre-converted to fp16 (same 11-bit mantissa as tf32).
// C[m,n] = sum_k V[m,k] * P[n,k]; both K-contiguous (row.col / NT).
// CTA tile 128x128, K-chunks of 32 halves (64B/row), 4-stage cp.async ring.
// smem rows: 20 uint32 stride (16 payload + 4 pad) -> conflict-free frags.
// =====================================================================
#define HSTR 20                      // smem row stride in uint32
#define HTILE (128 * HSTR)           // uint32 per operand tile (2560)
#define HSTAGE (2 * HTILE)           // A + B per stage (5120 words = 20480 B)
#define HNCH (NN / 32)               // 72 k-chunks
#define OV_SMEM (4 * HSTAGE * 4)     // 81920 bytes

__global__ __launch_bounds__(256, 2)
void ov_h_mma_kernel(const __half* __restrict__ Vh, const __half* __restrict__ Ph,
                     const float* __restrict__ X, float* __restrict__ O,
                     const float* __restrict__ gamma_p)
{
    extern __shared__ uint32_t smw[];

    const int tid = threadIdx.x;
    const long long bz = blockIdx.z;
    const __half* Vb = Vh + bz * (long long)(CC * NN);
    const __half* Pb = Ph + bz * (long long)(NN * NN);
    const float*  Xb = X + bz * (long long)(CC * NN);
    float*        Ob = O + bz * (long long)(CC * NN);

    const int m0 = blockIdx.y * 128;
    const int n0 = blockIdx.x * 128;

    // staging: thread t -> row t>>1 (0..127), 32B half (t&1)
    const int lrow = tid >> 1;
    const int lh   = tid & 1;
    const __half* gA = Vb + (long long)(m0 + lrow) * NN + lh * 16;
    const __half* gB = Pb + (long long)(n0 + lrow) * NN + lh * 16;
    const uint32_t sbase = smem_u32(smw);
    const uint32_t sA_st = sbase + (uint32_t)(lrow * HSTR + lh * 8) * 4u;
    const uint32_t sB_st = sA_st + HTILE * 4u;

#define OV_ISSUE(c)                                                        \
    do {                                                                   \
        const uint32_t off_ = (uint32_t)((c) & 3) * (HSTAGE * 4u);         \
        const __half* pa_ = gA + (c) * 32;                                 \
        const __half* pb_ = gB + (c) * 32;                                 \
        cp_async16(sA_st + off_,      pa_);                                \
        cp_async16(sA_st + off_ + 16, pa_ + 8);                            \
        cp_async16(sB_st + off_,      pb_);                                \
        cp_async16(sB_st + off_ + 16, pb_ + 8);                            \
        cp_commit();                                                       \
    } while (0)

    OV_ISSUE(0); OV_ISSUE(1); OV_ISSUE(2);

    const int wid  = tid >> 5, lane = tid & 31;
    const int wm   = (wid >> 2) * 64;    // warp m offset
    const int wn   = (wid & 3) * 32;     // warp n offset
    const int g4   = lane >> 2;          // groupID 0..7
    const int tg   = lane & 3;           // thread-in-group 0..3

    float acc[4][4][4];
    #pragma unroll
    for (int i = 0; i < 4; i++)
        #pragma unroll
        for (int j = 0; j < 4; j++)
            #pragma unroll
            for (int r = 0; r < 4; r++) acc[i][j][r] = 0.f;

    for (int c = 0; c < HNCH; c++) {
        if (c + 2 < HNCH)       cp_wait<2>();
        else if (c + 1 < HNCH)  cp_wait<1>();
        else                    cp_wait<0>();
        __syncthreads();

        if (c + 3 < HNCH) OV_ISSUE(c + 3);

        const uint32_t* A_ = smw + (c & 3) * HSTAGE;
        const uint32_t* B_ = A_ + HTILE;

        #pragma unroll
        for (int s = 0; s < 2; s++) {           // two k16 steps per chunk
            const int kw = s * 8 + tg;          // word index within row
            uint32_t a[4][4], b[4][2];
            #pragma unroll
            for (int mt = 0; mt < 4; mt++) {
                const int r0 = wm + mt * 16 + g4;
                a[mt][0] = A_[r0 * HSTR + kw];
                a[mt][1] = A_[(r0 + 8) * HSTR + kw];
                a[mt][2] = A_[r0 * HSTR + kw + 4];
                a[mt][3] = A_[(r0 + 8) * HSTR + kw + 4];
            }
            #pragma unroll
            for (int nt = 0; nt < 4; nt++) {
                const int nr = wn + nt * 8 + g4;
                b[nt][0] = B_[nr * HSTR + kw];
                b[nt][1] = B_[nr * HSTR + kw + 4];
            }
            #pragma unroll
            for (int mt = 0; mt < 4; mt++)
                #pragma unroll
                for (int nt = 0; nt < 4; nt++)
                    mma168816(acc[mt][nt], a[mt], b[nt]);
        }
    }

    const float g = *gamma_p;
    #pragma unroll
    for (int mt = 0; mt < 4; mt++) {
        #pragma unroll
        for (int half = 0; half < 2; half++) {
            const int m = m0 + wm + mt * 16 + g4 + half * 8;
            const long long rb = (long long)m * NN;
            #pragma unroll
            for (int nt = 0; nt < 4; nt++) {
                const int n = n0 + wn + nt * 8 + 2 * tg;
                float2 xr = *(const float2*)(Xb + rb + n);
                float2 o;
                o.x = fmaf(g, acc[mt][nt][half * 2 + 0], xr.x);
                o.y = fmaf(g, acc[mt][nt][half * 2 + 1], xr.y);
                *(float2*)(Ob + rb + n) = o;
            }
        }
    }
#undef OV_ISSUE
}

// =====================================================================
// v = Wv @ x via mma.sync tf32 (round-8 proven kernel); epilogue now
// stores fp16 V (same effective precision as the old fp32-store +
// consumer-side tf32 cvt).
// =====================================================================
#define OSTR 20
#define VBSTR 136
#define VATILE (128 * OSTR)
#define VBTILE (16 * VBSTR)
#define VSTAGE (VATILE + VBTILE)
#define VNCH (CC / 16)
#define VX_SMEM (4 * VSTAGE * 4)

__global__ __launch_bounds__(256, 2)
void vx_mma_kernel(const float* __restrict__ Wv, const float* __restrict__ x,
                   __half* __restrict__ Vout)
{
    extern __shared__ float sm[];

    const int tid = threadIdx.x;
    const long long bz = blockIdx.z;
    const float* xb = x + bz * (long long)(CC * NN);
    __half*      Vb = Vout + bz * (long long)(CC * NN);

    const int m0 = blockIdx.y * 128;
    const int n0 = blockIdx.x * 128;

    const int arow = tid >> 1;
    const int ac   = (tid & 1) * 8;
    const float* gA = Wv + (long long)(m0 + arow) * CC + ac;
    const int bk = tid >> 4;
    const int bn = (tid & 15) * 8;
    const float* gB = xb + (long long)bk * NN + n0 + bn;

    const uint32_t sbase = smem_u32(sm);
    const uint32_t sA_st = sbase + (uint32_t)(arow * OSTR + ac) * 4u;
    const uint32_t sB_st = sbase + (uint32_t)(VATILE + bk * VBSTR + bn) * 4u;

#define VX_ISSUE(c)                                                        \
    do {                                                                   \
        const uint32_t off_ = (uint32_t)((c) & 3) * (VSTAGE * 4u);         \
        const float* pa_ = gA + (c) * 16;                                  \
        const float* pb_ = gB + (long long)(c) * 16 * NN;                  \
        cp_async16(sA_st + off_,      pa_);                                \
        cp_async16(sA_st + off_ + 16, pa_ + 4);                            \
        cp_async16(sB_st + off_,      pb_);                                \
        cp_async16(sB_st + off_ + 16, pb_ + 4);                            \
        cp_commit();                                                       \
    } while (0)

    VX_ISSUE(0); VX_ISSUE(1); VX_ISSUE(2);

    const int wid  = tid >> 5, lane = tid & 31;
    const int wm   = (wid >> 2) * 64;
    const int wn   = (wid & 3) * 32;
    const int g4   = lane >> 2;
    const int tg   = lane & 3;

    float acc[4][4][4];
    #pragma unroll
    for (int i = 0; i < 4; i++)
        #pragma unroll
        for (int j = 0; j < 4; j++)
            #pragma unroll
            for (int r = 0; r < 4; r++) acc[i][j][r] = 0.f;

    for (int c = 0; c < VNCH; c++) {
        if (c + 2 < VNCH)       cp_wait<2>();
        else if (c + 1 < VNCH)  cp_wait<1>();
        else                    cp_wait<0>();
        __syncthreads();

        if (c + 3 < VNCH) VX_ISSUE(c + 3);

        const float* A_ = sm + (c & 3) * VSTAGE;
        const float* B_ = A_ + VATILE;

        #pragma unroll
        for (int s = 0; s < 2; s++) {
            const int kk = s * 8 + tg;
            uint32_t a[4][4], b[4][2];
            #pragma unroll
            for (int mt = 0; mt < 4; mt++) {
                const int r0 = wm + mt * 16 + g4;
                a[mt][0] = f2tf32(A_[r0 * OSTR + kk]);
                a[mt][1] = f2tf32(A_[(r0 + 8) * OSTR + kk]);
                a[mt][2] = f2tf32(A_[r0 * OSTR + kk + 4]);
                a[mt][3] = f2tf32(A_[(r0 + 8) * OSTR + kk + 4]);
            }
            #pragma unroll
            for (int nt = 0; nt < 4; nt++) {
                const int nr = wn + nt * 8 + g4;
                b[nt][0] = f2tf32(B_[kk * VBSTR + nr]);
                b[nt][1] = f2tf32(B_[(kk + 4) * VBSTR + nr]);
            }
            #pragma unroll
            for (int mt = 0; mt < 4; mt++)
                #pragma unroll
                for (int nt = 0; nt < 4; nt++)
                    mma16888(acc[mt][nt], a[mt], b[nt]);
        }
    }

    #pragma unroll
    for (int mt = 0; mt < 4; mt++) {
        #pragma unroll
        for (int half = 0; half < 2; half++) {
            const int m = m0 + wm + mt * 16 + g4 + half * 8;
            const long long rb = (long long)m * NN;
            #pragma unroll
            for (int nt = 0; nt < 4; nt++) {
                const int n = n0 + wn + nt * 8 + 2 * tg;
                __half2 h = __floats2half2_rn(acc[mt][nt][half * 2 + 0],
                                              acc[mt][nt][half * 2 + 1]);
                *(__half2*)(Vb + rb + n) = h;
            }
        }
    }
#undef VX_ISSUE
}

// ---------------- generic tiled SGEMM (fp32 SIMT, logit path) ----------------
static const int TM = 128, TN = 128, TK = 16;

template<bool AK, bool BK, bool EPI>
__global__ __launch_bounds__(256, 2)
void gemm_k(const float* __restrict__ A, const float* __restrict__ Bm,
            float* __restrict__ Cm, int M, int N, int K,
            long long sA, long long sB, long long sC,
            const float* __restrict__ R, long long sR,
            const float* __restrict__ gamma_p)
{
    A  += sA * (long long)blockIdx.z;
    Bm += sB * (long long)blockIdx.z;
    Cm += sC * (long long)blockIdx.z;
    if (EPI) R += sR * (long long)blockIdx.z;

    __shared__ float As[TK][TM];
    __shared__ float Bs[TK][TN];

    const int tid = threadIdx.x;
    const int n0 = blockIdx.x * TN;
    const int m0 = blockIdx.y * TM;
    const int tx = tid & 15;
    const int ty = tid >> 4;

    float acc[8][8];
    #pragma unroll
    for (int i = 0; i < 8; i++)
        #pragma unroll
        for (int j = 0; j < 8; j++) acc[i][j] = 0.f;

    for (int k0 = 0; k0 < K; k0 += TK) {
        if (AK) {
            const int row = tid >> 1;
            const int kc  = (tid & 1) * 8;
            const int m   = m0 + row;
            float4 v0 = make_float4(0.f, 0.f, 0.f, 0.f), v1 = v0;
            if (m < M) {
                const float* p = A + (long long)m * K + k0 + kc;
                v0 = *(const float4*)p;
                v1 = *(const float4*)(p + 4);
            }
            As[kc + 0][row] = v0.x; As[kc + 1][row] = v0.y;
            As[kc + 2][row] = v0.z; As[kc + 3][row] = v0.w;
            As[kc + 4][row] = v1.x; As[kc + 5][row] = v1.y;
            As[kc + 6][row] = v1.z; As[kc + 7][row] = v1.w;
        } else {
            const int kr = tid >> 4;
            const int mc = (tid & 15) * 8;
            const float* p = A + (long long)(k0 + kr) * M + m0 + mc;
            *(float4*)&As[kr][mc]     = *(const float4*)p;
            *(float4*)&As[kr][mc + 4] = *(const float4*)(p + 4);
        }
        if (!BK) {
            const int kr = tid >> 4;
            const int nc = (tid & 15) * 8;
            const float* p = Bm + (long long)(k0 + kr) * N + n0 + nc;
            *(float4*)&Bs[kr][nc]     = *(const float4*)p;
            *(float4*)&Bs[kr][nc + 4] = *(const float4*)(p + 4);
        } else {
            const int row = tid >> 1;
            const int kc  = (tid & 1) * 8;
            const float* p = Bm + (long long)(n0 + row) * K + k0 + kc;
            float4 v0 = *(const float4*)p;
            float4 v1 = *(const float4*)(p + 4);
            Bs[kc + 0][row] = v0.x; Bs[kc + 1][row] = v0.y;
            Bs[kc + 2][row] = v0.z; Bs[kc + 3][row] = v0.w;
            Bs[kc + 4][row] = v1.x; Bs[kc + 5][row] = v1.y;
            Bs[kc + 6][row] = v1.z; Bs[kc + 7][row] = v1.w;
        }
        __syncthreads();

        #pragma unroll
        for (int kk = 0; kk < TK; kk++) {
            float a[8], b[8];
            *(float4*)(a)     = *(const float4*)&As[kk][ty * 8];
            *(float4*)(a + 4) = *(const float4*)&As[kk][ty * 8 + 4];
            *(float4*)(b)     = *(const float4*)&Bs[kk][tx * 8];
            *(float4*)(b + 4) = *(const float4*)&Bs[kk][tx * 8 + 4];
            #pragma unroll
            for (int i = 0; i < 8; i++)
                #pragma unroll
                for (int j = 0; j < 8; j++)
                    acc[i][j] = fmaf(a[i], b[j], acc[i][j]);
        }
        __syncthreads();
    }

    const float g = EPI ? *gamma_p : 0.f;
    #pragma unroll
    for (int i = 0; i < 8; i++) {
        const int m = m0 + ty * 8 + i;
        if (m < M) {
            float* dst = Cm + (long long)m * N + n0 + tx * 8;
            if (EPI) {
                const float* r = R + (long long)m * N + n0 + tx * 8;
                float4 r0 = *(const float4*)r;
                float4 r1 = *(const float4*)(r + 4);
                float4 o0, o1;
                o0.x = fmaf(g, acc[i][0], r0.x); o0.y = fmaf(g, acc[i][1], r0.y);
                o0.z = fmaf(g, acc[i][2], r0.z); o0.w = fmaf(g, acc[i][3], r0.w);
                o1.x = fmaf(g, acc[i][4], r1.x); o1.y = fmaf(g, acc[i][5], r1.y);
                o1.z = fmaf(g, acc[i][6], r1.z); o1.w = fmaf(g, acc[i][7], r1.w);
                *(float4*)dst       = o0;
                *(float4*)(dst + 4) = o1;
            } else {
                float4 o0 = make_float4(acc[i][0], acc[i][1], acc[i][2], acc[i][3]);
                float4 o1 = make_float4(acc[i][4], acc[i][5], acc[i][6], acc[i][7]);
                *(float4*)dst       = o0;
                *(float4*)(dst + 4) = o1;
            }
        }
    }
}

// ---------------- row softmax; reads fp32 S, writes fp16 P ----------------
__global__ __launch_bounds__(256)
void softmax_rows(const float* __restrict__ S, __half* __restrict__ P)
{
    __shared__ float red[8];
    const float* p = S + (size_t)blockIdx.x * NN;
    __half*      o = P + (size_t)blockIdx.x * NN;
    const int tid  = threadIdx.x;
    const int lane = tid & 31;
    const int wid  = tid >> 5;

    float v[9];
    float m = -1e30f;
    #pragma unroll
    for (int j = 0; j < 9; j++) {
        v[j] = p[tid + 256 * j];
        m = fmaxf(m, v[j]);
    }
    #pragma unroll
    for (int ofs = 16; ofs; ofs >>= 1) m = fmaxf(m, __shfl_xor_sync(0xffffffffu, m, ofs));
    if (lane == 0) red[wid] = m;
    __syncthreads();
    m = red[0];
    #pragma unroll
    for (int i = 1; i < 8; i++) m = fmaxf(m, red[i]);
    __syncthreads();

    float s = 0.f;
    #pragma unroll
    for (int j = 0; j < 9; j++) {
        v[j] = expf(v[j] - m);
        s += v[j];
    }
    #pragma unroll
    for (int ofs = 16; ofs; ofs >>= 1) s += __shfl_xor_sync(0xffffffffu, s, ofs);
    if (lane == 0) red[wid] = s;
    __syncthreads();
    s = 0.f;
    #pragma unroll
    for (int i = 0; i < 8; i++) s += red[i];

    const float inv = 1.f / s;
    #pragma unroll
    for (int j = 0; j < 9; j++)
        o[tid + 256 * j] = __float2half_rn(v[j] * inv);
}

// ---------------- launch ----------------
extern "C" void kernel_launch(void* const* d_in, const int* in_sizes, int n_in,
                              void* d_out, int out_size)
{
    const float* x     = (const float*)d_in[0];   // (16,512,48,48)
    const float* Wq    = (const float*)d_in[1];   // (64,512)
    const float* Wk    = (const float*)d_in[2];   // (64,512)
    const float* Wv    = (const float*)d_in[3];   // (512,512)
    const float* gamma = (const float*)d_in[4];   // (1,)
    float* out = (float*)d_out;

    float *q, *k, *s;
    __half *ph, *vh;
    cudaGetSymbolAddress((void**)&q,  g_q);
    cudaGetSymbolAddress((void**)&k,  g_k);
    cudaGetSymbolAddress((void**)&s,  g_s);
    cudaGetSymbolAddress((void**)&ph, g_ph);
    cudaGetSymbolAddress((void**)&vh, g_vh);

    const long long sX = (long long)CC * NN;
    const long long sQ = (long long)II * NN;
    const long long sS = (long long)NN * NN;

    dim3 blk(256);

    // q = Wq @ x, k = Wk @ x  (fp32 SIMT)
    gemm_k<true, false, false><<<dim3(NN / TN, 1, BB), blk>>>(
        Wq, x, q, II, NN, CC, 0, sX, sQ, nullptr, 0, nullptr);
    gemm_k<true, false, false><<<dim3(NN / TN, 1, BB), blk>>>(
        Wk, x, k, II, NN, CC, 0, sX, sQ, nullptr, 0, nullptr);

    // v = Wv @ x  (tf32 mma; stores fp16 V)
    cudaFuncSetAttribute(vx_mma_kernel,
                         cudaFuncAttributeMaxDynamicSharedMemorySize, VX_SMEM);
    vx_mma_kernel<<<dim3(NN / 128, CC / 128, BB), blk, VX_SMEM>>>(Wv, x, vh);

    // S = q^T @ k  (fp32 SIMT — logits stay accurate)
    gemm_k<false, false, false><<<dim3(NN / TN, NN / TM, BB), blk>>>(
        q, k, s, NN, NN, II, sQ, sQ, sS, nullptr, 0, nullptr);

    // P = softmax(S), emitted fp16
    softmax_rows<<<BB * NN, 256>>>(s, ph);

    // out = gamma * (V @ P^T) + x  (fp16 mma, fp32 accumulate)
    cudaFuncSetAttribute(ov_h_mma_kernel,
                         cudaFuncAttributeMaxDynamicSharedMemorySize, OV_SMEM);
    ov_h_mma_kernel<<<dim3(NN / 128, CC / 128, BB), blk, OV_SMEM>>>(
        vh, ph, x, out, gamma);
}

// round 10
// speedup vs baseline: 2.1470x; 1.1362x over previous
#include <cuda_runtime.h>
#include <cuda_fp16.h>
#include <stdint.h>
#include <math.h>

// Problem constants
#define BB 16
#define CC 512
#define NN 2304      // 48*48
#define II 64

// ---------------- scratch (static device globals; no allocation) ----------------
__device__ float  g_q[(size_t)BB * II * NN];          //   9 MB fp32 q  [i][n]
__device__ float  g_k[(size_t)BB * II * NN];          //   9 MB fp32 k  [i][n]
__device__ __half g_qth[(size_t)BB * NN * II];        // 4.7 MB qT hi [n][i]
__device__ __half g_qtl[(size_t)BB * NN * II];        // 4.7 MB qT lo
__device__ __half g_kth[(size_t)BB * NN * II];        // 4.7 MB kT hi [m][i]
__device__ __half g_ktl[(size_t)BB * NN * II];        // 4.7 MB kT lo
__device__ float  g_s[(size_t)BB * NN * NN];          // 324 MB fp32 logits S
__device__ __half g_ph[(size_t)BB * NN * NN];         // 162 MB fp16 softmax P
__device__ __half g_vh[(size_t)BB * CC * NN];         //  36 MB fp16 V

// =====================================================================
// helpers
// =====================================================================
__device__ __forceinline__ uint32_t smem_u32(const void* p) {
    uint32_t a;
    asm("{ .reg .u64 t; cvta.to.shared.u64 t, %1; cvt.u32.u64 %0, t; }"
        : "=r"(a) : "l"(p));
    return a;
}

__device__ __forceinline__ void cp_async16(uint32_t saddr, const void* gptr) {
    asm volatile("cp.async.cg.shared.global [%0], [%1], 16;"
                 :: "r"(saddr), "l"(gptr) : "memory");
}
__device__ __forceinline__ void cp_commit() {
    asm volatile("cp.async.commit_group;" ::: "memory");
}
template<int N>
__device__ __forceinline__ void cp_wait() {
    asm volatile("cp.async.wait_group %0;" :: "n"(N) : "memory");
}

__device__ __forceinline__ uint32_t f2tf32(float f) {
    uint32_t u;
    asm("cvt.rna.tf32.f32 %0, %1;" : "=r"(u) : "f"(f));
    return u;
}

// tf32: D += A(16x8) * B(8x8)
__device__ __forceinline__ void mma16888(float* d, const uint32_t* a, const uint32_t* b) {
    asm volatile(
        "mma.sync.aligned.m16n8k8.row.col.f32.tf32.tf32.f32 "
        "{%0,%1,%2,%3}, {%4,%5,%6,%7}, {%8,%9}, {%0,%1,%2,%3};"
        : "+f"(d[0]), "+f"(d[1]), "+f"(d[2]), "+f"(d[3])
        : "r"(a[0]), "r"(a[1]), "r"(a[2]), "r"(a[3]), "r"(b[0]), "r"(b[1]));
}

// fp16: D += A(16x16) * B(16x8), fp32 accumulate
__device__ __forceinline__ void mma168816(float* d, const uint32_t* a, const uint32_t* b) {
    asm volatile(
        "mma.sync.aligned.m16n8k16.row.col.f32.f16.f16.f32 "
        "{%0,%1,%2,%3}, {%4,%5,%6,%7}, {%8,%9}, {%0,%1,%2,%3};"
        : "+f"(d[0]), "+f"(d[1]), "+f"(d[2]), "+f"(d[3])
        : "r"(a[0]), "r"(a[1]), "r"(a[2]), "r"(a[3]), "r"(b[0]), "r"(b[1]));
}

// =====================================================================
// transpose + fp16 split: q/k [i][n] fp32 -> qT/kT [n][i] (hi, lo) fp16
// grid (NN/64, 2, BB), block 256
// =====================================================================
__global__ __launch_bounds__(256)
void tsplit_kernel()
{
    __shared__ float t[64][65];
    const long long bz = blockIdx.z;
    const int n0 = blockIdx.x * 64;
    const bool isq = (blockIdx.y == 0);
    const float* src = (isq ? g_q : g_k) + bz * (long long)(II * NN);
    __half* dh = (isq ? g_qth : g_kth) + bz * (long long)(NN * II);
    __half* dl = (isq ? g_qtl : g_ktl) + bz * (long long)(NN * II);

    const int t4 = threadIdx.x & 3;
    const int r  = threadIdx.x >> 2;     // 0..63

    // read 64 (i) x 64 (n) tile, coalesced along n
    #pragma unroll
    for (int j = 0; j < 4; j++) {
        float4 v = *(const float4*)(src + (long long)r * NN + n0 + t4 * 16 + j * 4);
        t[r][t4 * 16 + j * 4 + 0] = v.x;
        t[r][t4 * 16 + j * 4 + 1] = v.y;
        t[r][t4 * 16 + j * 4 + 2] = v.z;
        t[r][t4 * 16 + j * 4 + 3] = v.w;
    }
    __syncthreads();

    // write transposed rows [n][i], 16 i-values per thread, hi/lo split
    const long long ob = (long long)(n0 + r) * II + t4 * 16;
    #pragma unroll
    for (int w = 0; w < 8; w++) {
        float v0 = t[t4 * 16 + 2 * w + 0][r];
        float v1 = t[t4 * 16 + 2 * w + 1][r];
        __half h0 = __float2half_rn(v0);
        __half h1 = __float2half_rn(v1);
        __half l0 = __float2half_rn(v0 - __half2float(h0));
        __half l1 = __float2half_rn(v1 - __half2float(h1));
        *(__half2*)(dh + ob + 2 * w) = __halves2half2(h0, h1);
        *(__half2*)(dl + ob + 2 * w) = __halves2half2(l0, l1);
    }
}

// =====================================================================
// S[n,m] = sum_i q[i,n]*k[i,m] via split-fp16 mma (hi*hi + hi*lo + lo*hi)
// A = qT[n][64], B = kT[m][64], both row-major hi/lo fp16. fp32 out.
// CTA tile 128x128; K=64 fits in one shot (no pipeline).
// =====================================================================
#define SSTR 36                         // smem row stride in words (64 halves + 8 pad)
#define STILE (128 * SSTR)              // words per tile (4608)
#define S_SMEM (4 * STILE * 4)          // 73728 bytes: qh, ql, kh, kl

__global__ __launch_bounds__(256, 2)
void s_mma_kernel(const __half* __restrict__ qth, const __half* __restrict__ qtl,
                  const __half* __restrict__ kth, const __half* __restrict__ ktl,
                  float* __restrict__ S)
{
    extern __shared__ uint32_t sw[];
    const int tid = threadIdx.x;
    const long long bz = blockIdx.z;
    qth += bz * (long long)(NN * II);
    qtl += bz * (long long)(NN * II);
    kth += bz * (long long)(NN * II);
    ktl += bz * (long long)(NN * II);
    S   += bz * (long long)NN * NN;

    const int n0 = blockIdx.y * 128;    // S row tile (A)
    const int m0 = blockIdx.x * 128;    // S col tile (B)

    // stage 4 tiles: thread -> row tid>>1, 32-half segment tid&1
    {
        const int lr = tid >> 1;
        const int lsg = tid & 1;
        const uint32_t base = smem_u32(sw);
        const uint32_t sd = base + (uint32_t)(lr * SSTR + lsg * 16) * 4u;
        const long long go = (long long)lr * II + lsg * 32;
        const __half* s0 = qth + (long long)n0 * II + go;
        const __half* s1 = qtl + (long long)n0 * II + go;
        const __half* s2 = kth + (long long)m0 * II + go;
        const __half* s3 = ktl + (long long)m0 * II + go;
        #pragma unroll
        for (int c = 0; c < 4; c++) {
            cp_async16(sd + 0 * STILE * 4 + c * 16, s0 + c * 8);
            cp_async16(sd + 1 * STILE * 4 + c * 16, s1 + c * 8);
            cp_async16(sd + 2 * STILE * 4 + c * 16, s2 + c * 8);
            cp_async16(sd + 3 * STILE * 4 + c * 16, s3 + c * 8);
        }
        cp_commit();
    }
    cp_wait<0>();
    __syncthreads();

    const int wid  = tid >> 5, lane = tid & 31;
    const int wm   = (wid >> 2) * 64;
    const int wn   = (wid & 3) * 32;
    const int g4   = lane >> 2;
    const int tg   = lane & 3;

    float acc[4][4][4];
    #pragma unroll
    for (int i = 0; i < 4; i++)
        #pragma unroll
        for (int j = 0; j < 4; j++)
            #pragma unroll
            for (int r = 0; r < 4; r++) acc[i][j][r] = 0.f;

    const uint32_t* QH = sw;
    const uint32_t* QL = sw + STILE;
    const uint32_t* KH = sw + 2 * STILE;
    const uint32_t* KL = sw + 3 * STILE;

    #pragma unroll
    for (int p = 0; p < 3; p++) {       // hi*hi, hi*lo, lo*hi
        const uint32_t* A_ = (p == 2) ? QL : QH;
        const uint32_t* B_ = (p == 1) ? KL : KH;
        #pragma unroll
        for (int s = 0; s < 4; s++) {   // 4 x k16 steps = K 64
            const int kw = s * 8 + tg;
            uint32_t a[4][4], b[4][2];
            #pragma unroll
            for (int mt = 0; mt < 4; mt++) {
                const int r0 = wm + mt * 16 + g4;
                a[mt][0] = A_[r0 * SSTR + kw];
                a[mt][1] = A_[(r0 + 8) * SSTR + kw];
                a[mt][2] = A_[r0 * SSTR + kw + 4];
                a[mt][3] = A_[(r0 + 8) * SSTR + kw + 4];
            }
            #pragma unroll
            for (int nt = 0; nt < 4; nt++) {
                const int nr = wn + nt * 8 + g4;
                b[nt][0] = B_[nr * SSTR + kw];
                b[nt][1] = B_[nr * SSTR + kw + 4];
            }
            #pragma unroll
            for (int mt = 0; mt < 4; mt++)
                #pragma unroll
                for (int nt = 0; nt < 4; nt++)
                    mma168816(acc[mt][nt], a[mt], b[nt]);
        }
    }

    // epilogue: fp32 S
    #pragma unroll
    for (int mt = 0; mt < 4; mt++) {
        #pragma unroll
        for (int hf = 0; hf < 2; hf++) {
            const int row = n0 + wm + mt * 16 + g4 + hf * 8;
            const long long rb = (long long)row * NN;
            #pragma unroll
            for (int nt = 0; nt < 4; nt++) {
                const int col = m0 + wn + nt * 8 + 2 * tg;
                float2 o;
                o.x = acc[mt][nt][hf * 2 + 0];
                o.y = acc[mt][nt][hf * 2 + 1];
                *(float2*)(S + rb + col) = o;
            }
        }
    }
}

// =====================================================================
// O = gamma * (V @ P^T) + X via fp16 mma (round-9 proven kernel)
// =====================================================================
#define HSTR 20
#define HTILE (128 * HSTR)
#define HSTAGE (2 * HTILE)
#define HNCH (NN / 32)
#define OV_SMEM (4 * HSTAGE * 4)

__global__ __launch_bounds__(256, 2)
void ov_h_mma_kernel(const __half* __restrict__ Vh, const __half* __restrict__ Ph,
                     const float* __restrict__ X, float* __restrict__ O,
                     const float* __restrict__ gamma_p)
{
    extern __shared__ uint32_t smw[];

    const int tid = threadIdx.x;
    const long long bz = blockIdx.z;
    const __half* Vb = Vh + bz * (long long)(CC * NN);
    const __half* Pb = Ph + bz * (long long)(NN * NN);
    const float*  Xb = X + bz * (long long)(CC * NN);
    float*        Ob = O + bz * (long long)(CC * NN);

    const int m0 = blockIdx.y * 128;
    const int n0 = blockIdx.x * 128;

    const int lrow = tid >> 1;
    const int lh   = tid & 1;
    const __half* gA = Vb + (long long)(m0 + lrow) * NN + lh * 16;
    const __half* gB = Pb + (long long)(n0 + lrow) * NN + lh * 16;
    const uint32_t sbase = smem_u32(smw);
    const uint32_t sA_st = sbase + (uint32_t)(lrow * HSTR + lh * 8) * 4u;
    const uint32_t sB_st = sA_st + HTILE * 4u;

#define OV_ISSUE(c)                                                        \
    do {                                                                   \
        const uint32_t off_ = (uint32_t)((c) & 3) * (HSTAGE * 4u);         \
        const __half* pa_ = gA + (c) * 32;                                 \
        const __half* pb_ = gB + (c) * 32;                                 \
        cp_async16(sA_st + off_,      pa_);                                \
        cp_async16(sA_st + off_ + 16, pa_ + 8);                            \
        cp_async16(sB_st + off_,      pb_);                                \
        cp_async16(sB_st + off_ + 16, pb_ + 8);                            \
        cp_commit();                                                       \
    } while (0)

    OV_ISSUE(0); OV_ISSUE(1); OV_ISSUE(2);

    const int wid  = tid >> 5, lane = tid & 31;
    const int wm   = (wid >> 2) * 64;
    const int wn   = (wid & 3) * 32;
    const int g4   = lane >> 2;
    const int tg   = lane & 3;

    float acc[4][4][4];
    #pragma unroll
    for (int i = 0; i < 4; i++)
        #pragma unroll
        for (int j = 0; j < 4; j++)
            #pragma unroll
            for (int r = 0; r < 4; r++) acc[i][j][r] = 0.f;

    for (int c = 0; c < HNCH; c++) {
        if (c + 2 < HNCH)       cp_wait<2>();
        else if (c + 1 < HNCH)  cp_wait<1>();
        else                    cp_wait<0>();
        __syncthreads();

        if (c + 3 < HNCH) OV_ISSUE(c + 3);

        const uint32_t* A_ = smw + (c & 3) * HSTAGE;
        const uint32_t* B_ = A_ + HTILE;

        #pragma unroll
        for (int s = 0; s < 2; s++) {
            const int kw = s * 8 + tg;
            uint32_t a[4][4], b[4][2];
            #pragma unroll
            for (int mt = 0; mt < 4; mt++) {
                const int r0 = wm + mt * 16 + g4;
                a[mt][0] = A_[r0 * HSTR + kw];
                a[mt][1] = A_[(r0 + 8) * HSTR + kw];
                a[mt][2] = A_[r0 * HSTR + kw + 4];
                a[mt][3] = A_[(r0 + 8) * HSTR + kw + 4];
            }
            #pragma unroll
            for (int nt = 0; nt < 4; nt++) {
                const int nr = wn + nt * 8 + g4;
                b[nt][0] = B_[nr * HSTR + kw];
                b[nt][1] = B_[nr * HSTR + kw + 4];
            }
            #pragma unroll
            for (int mt = 0; mt < 4; mt++)
                #pragma unroll
                for (int nt = 0; nt < 4; nt++)
                    mma168816(acc[mt][nt], a[mt], b[nt]);
        }
    }

    const float g = *gamma_p;
    #pragma unroll
    for (int mt = 0; mt < 4; mt++) {
        #pragma unroll
        for (int hf = 0; hf < 2; hf++) {
            const int m = m0 + wm + mt * 16 + g4 + hf * 8;
            const long long rb = (long long)m * NN;
            #pragma unroll
            for (int nt = 0; nt < 4; nt++) {
                const int n = n0 + wn + nt * 8 + 2 * tg;
                float2 xr = *(const float2*)(Xb + rb + n);
                float2 o;
                o.x = fmaf(g, acc[mt][nt][hf * 2 + 0], xr.x);
                o.y = fmaf(g, acc[mt][nt][hf * 2 + 1], xr.y);
                *(float2*)(Ob + rb + n) = o;
            }
        }
    }
#undef OV_ISSUE
}

// =====================================================================
// v = Wv @ x via tf32 mma; stores fp16 V (round-9 proven kernel)
// =====================================================================
#define OSTR 20
#define VBSTR 136
#define VATILE (128 * OSTR)
#define VBTILE (16 * VBSTR)
#define VSTAGE (VATILE + VBTILE)
#define VNCH (CC / 16)
#define VX_SMEM (4 * VSTAGE * 4)

__global__ __launch_bounds__(256, 2)
void vx_mma_kernel(const float* __restrict__ Wv, const float* __restrict__ x,
                   __half* __restrict__ Vout)
{
    extern __shared__ float sm[];

    const int tid = threadIdx.x;
    const long long bz = blockIdx.z;
    const float* xb = x + bz * (long long)(CC * NN);
    __half*      Vb = Vout + bz * (long long)(CC * NN);

    const int m0 = blockIdx.y * 128;
    const int n0 = blockIdx.x * 128;

    const int arow = tid >> 1;
    const int ac   = (tid & 1) * 8;
    const float* gA = Wv + (long long)(m0 + arow) * CC + ac;
    const int bk = tid >> 4;
    const int bn = (tid & 15) * 8;
    const float* gB = xb + (long long)bk * NN + n0 + bn;

    const uint32_t sbase = smem_u32(sm);
    const uint32_t sA_st = sbase + (uint32_t)(arow * OSTR + ac) * 4u;
    const uint32_t sB_st = sbase + (uint32_t)(VATILE + bk * VBSTR + bn) * 4u;

#define VX_ISSUE(c)                                                        \
    do {                                                                   \
        const uint32_t off_ = (uint32_t)((c) & 3) * (VSTAGE * 4u);         \
        const float* pa_ = gA + (c) * 16;                                  \
        const float* pb_ = gB + (long long)(c) * 16 * NN;                  \
        cp_async16(sA_st + off_,      pa_);                                \
        cp_async16(sA_st + off_ + 16, pa_ + 4);                            \
        cp_async16(sB_st + off_,      pb_);                                \
        cp_async16(sB_st + off_ + 16, pb_ + 4);                            \
        cp_commit();                                                       \
    } while (0)

    VX_ISSUE(0); VX_ISSUE(1); VX_ISSUE(2);

    const int wid  = tid >> 5, lane = tid & 31;
    const int wm   = (wid >> 2) * 64;
    const int wn   = (wid & 3) * 32;
    const int g4   = lane >> 2;
    const int tg   = lane & 3;

    float acc[4][4][4];
    #pragma unroll
    for (int i = 0; i < 4; i++)
        #pragma unroll
        for (int j = 0; j < 4; j++)
            #pragma unroll
            for (int r = 0; r < 4; r++) acc[i][j][r] = 0.f;

    for (int c = 0; c < VNCH; c++) {
        if (c + 2 < VNCH)       cp_wait<2>();
        else if (c + 1 < VNCH)  cp_wait<1>();
        else                    cp_wait<0>();
        __syncthreads();

        if (c + 3 < VNCH) VX_ISSUE(c + 3);

        const float* A_ = sm + (c & 3) * VSTAGE;
        const float* B_ = A_ + VATILE;

        #pragma unroll
        for (int s = 0; s < 2; s++) {
            const int kk = s * 8 + tg;
            uint32_t a[4][4], b[4][2];
            #pragma unroll
            for (int mt = 0; mt < 4; mt++) {
                const int r0 = wm + mt * 16 + g4;
                a[mt][0] = f2tf32(A_[r0 * OSTR + kk]);
                a[mt][1] = f2tf32(A_[(r0 + 8) * OSTR + kk]);
                a[mt][2] = f2tf32(A_[r0 * OSTR + kk + 4]);
                a[mt][3] = f2tf32(A_[(r0 + 8) * OSTR + kk + 4]);
            }
            #pragma unroll
            for (int nt = 0; nt < 4; nt++) {
                const int nr = wn + nt * 8 + g4;
                b[nt][0] = f2tf32(B_[kk * VBSTR + nr]);
                b[nt][1] = f2tf32(B_[(kk + 4) * VBSTR + nr]);
            }
            #pragma unroll
            for (int mt = 0; mt < 4; mt++)
                #pragma unroll
                for (int nt = 0; nt < 4; nt++)
                    mma16888(acc[mt][nt], a[mt], b[nt]);
        }
    }

    #pragma unroll
    for (int mt = 0; mt < 4; mt++) {
        #pragma unroll
        for (int hf = 0; hf < 2; hf++) {
            const int m = m0 + wm + mt * 16 + g4 + hf * 8;
            const long long rb = (long long)m * NN;
            #pragma unroll
            for (int nt = 0; nt < 4; nt++) {
                const int n = n0 + wn + nt * 8 + 2 * tg;
                __half2 h = __floats2half2_rn(acc[mt][nt][hf * 2 + 0],
                                              acc[mt][nt][hf * 2 + 1]);
                *(__half2*)(Vb + rb + n) = h;
            }
        }
    }
#undef VX_ISSUE
}

// ---------------- generic tiled SGEMM (fp32 SIMT, q/k producers) ----------------
static const int TM = 128, TN = 128, TK = 16;

template<bool AK, bool BK, bool EPI>
__global__ __launch_bounds__(256, 2)
void gemm_k(const float* __restrict__ A, const float* __restrict__ Bm,
            float* __restrict__ Cm, int M, int N, int K,
            long long sA, long long sB, long long sC,
            const float* __restrict__ R, long long sR,
            const float* __restrict__ gamma_p)
{
    A  += sA * (long long)blockIdx.z;
    Bm += sB * (long long)blockIdx.z;
    Cm += sC * (long long)blockIdx.z;
    if (EPI) R += sR * (long long)blockIdx.z;

    __shared__ float As[TK][TM];
    __shared__ float Bs[TK][TN];

    const int tid = threadIdx.x;
    const int n0 = blockIdx.x * TN;
    const int m0 = blockIdx.y * TM;
    const int tx = tid & 15;
    const int ty = tid >> 4;

    float acc[8][8];
    #pragma unroll
    for (int i = 0; i < 8; i++)
        #pragma unroll
        for (int j = 0; j < 8; j++) acc[i][j] = 0.f;

    for (int k0 = 0; k0 < K; k0 += TK) {
        if (AK) {
            const int row = tid >> 1;
            const int kc  = (tid & 1) * 8;
            const int m   = m0 + row;
            float4 v0 = make_float4(0.f, 0.f, 0.f, 0.f), v1 = v0;
            if (m < M) {
                const float* p = A + (long long)m * K + k0 + kc;
                v0 = *(const float4*)p;
                v1 = *(const float4*)(p + 4);
            }
            As[kc + 0][row] = v0.x; As[kc + 1][row] = v0.y;
            As[kc + 2][row] = v0.z; As[kc + 3][row] = v0.w;
            As[kc + 4][row] = v1.x; As[kc + 5][row] = v1.y;
            As[kc + 6][row] = v1.z; As[kc + 7][row] = v1.w;
        } else {
            const int kr = tid >> 4;
            const int mc = (tid & 15) * 8;
            const float* p = A + (long long)(k0 + kr) * M + m0 + mc;
            *(float4*)&As[kr][mc]     = *(const float4*)p;
            *(float4*)&As[kr][mc + 4] = *(const float4*)(p + 4);
        }
        if (!BK) {
            const int kr = tid >> 4;
            const int nc = (tid & 15) * 8;
            const float* p = Bm + (long long)(k0 + kr) * N + n0 + nc;
            *(float4*)&Bs[kr][nc]     = *(const float4*)p;
            *(float4*)&Bs[kr][nc + 4] = *(const float4*)(p + 4);
        } else {
            const int row = tid >> 1;
            const int kc  = (tid & 1) * 8;
            const float* p = Bm + (long long)(n0 + row) * K + k0 + kc;
            float4 v0 = *(const float4*)p;
            float4 v1 = *(const float4*)(p + 4);
            Bs[kc + 0][row] = v0.x; Bs[kc + 1][row] = v0.y;
            Bs[kc + 2][row] = v0.z; Bs[kc + 3][row] = v0.w;
            Bs[kc + 4][row] = v1.x; Bs[kc + 5][row] = v1.y;
            Bs[kc + 6][row] = v1.z; Bs[kc + 7][row] = v1.w;
        }
        __syncthreads();

        #pragma unroll
        for (int kk = 0; kk < TK; kk++) {
            float a[8], b[8];
            *(float4*)(a)     = *(const float4*)&As[kk][ty * 8];
            *(float4*)(a + 4) = *(const float4*)&As[kk][ty * 8 + 4];
            *(float4*)(b)     = *(const float4*)&Bs[kk][tx * 8];
            *(float4*)(b + 4) = *(const float4*)&Bs[kk][tx * 8 + 4];
            #pragma unroll
            for (int i = 0; i < 8; i++)
                #pragma unroll
                for (int j = 0; j < 8; j++)
                    acc[i][j] = fmaf(a[i], b[j], acc[i][j]);
        }
        __syncthreads();
    }

    const float g = EPI ? *gamma_p : 0.f;
    #pragma unroll
    for (int i = 0; i < 8; i++) {
        const int m = m0 + ty * 8 + i;
        if (m < M) {
            float* dst = Cm + (long long)m * N + n0 + tx * 8;
            if (EPI) {
                const float* r = R + (long long)m * N + n0 + tx * 8;
                float4 r0 = *(const float4*)r;
                float4 r1 = *(const float4*)(r + 4);
                float4 o0, o1;
                o0.x = fmaf(g, acc[i][0], r0.x); o0.y = fmaf(g, acc[i][1], r0.y);
                o0.z = fmaf(g, acc[i][2], r0.z); o0.w = fmaf(g, acc[i][3], r0.w);
                o1.x = fmaf(g, acc[i][4], r1.x); o1.y = fmaf(g, acc[i][5], r1.y);
                o1.z = fmaf(g, acc[i][6], r1.z); o1.w = fmaf(g, acc[i][7], r1.w);
                *(float4*)dst       = o0;
                *(float4*)(dst + 4) = o1;
            } else {
                float4 o0 = make_float4(acc[i][0], acc[i][1], acc[i][2], acc[i][3]);
                float4 o1 = make_float4(acc[i][4], acc[i][5], acc[i][6], acc[i][7]);
                *(float4*)dst       = o0;
                *(float4*)(dst + 4) = o1;
            }
        }
    }
}

// ---------------- row softmax; reads fp32 S, writes fp16 P ----------------
__global__ __launch_bounds__(256)
void softmax_rows(const float* __restrict__ S, __half* __restrict__ P)
{
    __shared__ float red[8];
    const float* p = S + (size_t)blockIdx.x * NN;
    __half*      o = P + (size_t)blockIdx.x * NN;
    const int tid  = threadIdx.x;
    const int lane = tid & 31;
    const int wid  = tid >> 5;

    float v[9];
    float m = -1e30f;
    #pragma unroll
    for (int j = 0; j < 9; j++) {
        v[j] = p[tid + 256 * j];
        m = fmaxf(m, v[j]);
    }
    #pragma unroll
    for (int ofs = 16; ofs; ofs >>= 1) m = fmaxf(m, __shfl_xor_sync(0xffffffffu, m, ofs));
    if (lane == 0) red[wid] = m;
    __syncthreads();
    m = red[0];
    #pragma unroll
    for (int i = 1; i < 8; i++) m = fmaxf(m, red[i]);
    __syncthreads();

    float s = 0.f;
    #pragma unroll
    for (int j = 0; j < 9; j++) {
        v[j] = expf(v[j] - m);
        s += v[j];
    }
    #pragma unroll
    for (int ofs = 16; ofs; ofs >>= 1) s += __shfl_xor_sync(0xffffffffu, s, ofs);
    if (lane == 0) red[wid] = s;
    __syncthreads();
    s = 0.f;
    #pragma unroll
    for (int i = 0; i < 8; i++) s += red[i];

    const float inv = 1.f / s;
    #pragma unroll
    for (int j = 0; j < 9; j++)
        o[tid + 256 * j] = __float2half_rn(v[j] * inv);
}

// ---------------- launch ----------------
extern "C" void kernel_launch(void* const* d_in, const int* in_sizes, int n_in,
                              void* d_out, int out_size)
{
    const float* x     = (const float*)d_in[0];   // (16,512,48,48)
    const float* Wq    = (const float*)d_in[1];   // (64,512)
    const float* Wk    = (const float*)d_in[2];   // (64,512)
    const float* Wv    = (const float*)d_in[3];   // (512,512)
    const float* gamma = (const float*)d_in[4];   // (1,)
    float* out = (float*)d_out;

    float *q, *k, *s;
    __half *ph, *vh, *qth, *qtl, *kth, *ktl;
    cudaGetSymbolAddress((void**)&q,   g_q);
    cudaGetSymbolAddress((void**)&k,   g_k);
    cudaGetSymbolAddress((void**)&s,   g_s);
    cudaGetSymbolAddress((void**)&ph,  g_ph);
    cudaGetSymbolAddress((void**)&vh,  g_vh);
    cudaGetSymbolAddress((void**)&qth, g_qth);
    cudaGetSymbolAddress((void**)&qtl, g_qtl);
    cudaGetSymbolAddress((void**)&kth, g_kth);
    cudaGetSymbolAddress((void**)&ktl, g_ktl);

    const long long sX = (long long)CC * NN;
    const long long sQ = (long long)II * NN;

    dim3 blk(256);

    // q = Wq @ x, k = Wk @ x  (fp32 SIMT)
    gemm_k<true, false, false><<<dim3(NN / TN, 1, BB), blk>>>(
        Wq, x, q, II, NN, CC, 0, sX, sQ, nullptr, 0, nullptr);
    gemm_k<true, false, false><<<dim3(NN / TN, 1, BB), blk>>>(
        Wk, x, k, II, NN, CC, 0, sX, sQ, nullptr, 0, nullptr);

    // v = Wv @ x  (tf32 mma; stores fp16 V)
    cudaFuncSetAttribute(vx_mma_kernel,
                         cudaFuncAttributeMaxDynamicSharedMemorySize, VX_SMEM);
    vx_mma_kernel<<<dim3(NN / 128, CC / 128, BB), blk, VX_SMEM>>>(Wv, x, vh);

    // transpose + fp16 split of q, k
    tsplit_kernel<<<dim3(NN / 64, 2, BB), blk>>>();

    // S = q^T @ k  (split-fp16 mma, fp32-grade accuracy)
    cudaFuncSetAttribute(s_mma_kernel,
                         cudaFuncAttributeMaxDynamicSharedMemorySize, S_SMEM);
    s_mma_kernel<<<dim3(NN / 128, NN / 128, BB), blk, S_SMEM>>>(
        qth, qtl, kth, ktl, s);

    // P = softmax(S), emitted fp16
    softmax_rows<<<BB * NN, 256>>>(s, ph);

    // out = gamma * (V @ P^T) + x  (fp16 mma, fp32 accumulate)
    cudaFuncSetAttribute(ov_h_mma_kernel,
                         cudaFuncAttributeMaxDynamicSharedMemorySize, OV_SMEM);
    ov_h_mma_kernel<<<dim3(NN / 128, CC / 128, BB), blk, OV_SMEM>>>(
        vh, ph, x, out, gamma);
}

// round 11
// speedup vs baseline: 2.4860x; 1.1579x over previous
#include <cuda_runtime.h>
#include <cuda_fp16.h>
#include <stdint.h>
#include <math.h>

// Problem constants
#define BB 16
#define CC 512
#define NN 2304      // 48*48
#define II 64

// ---------------- scratch (static device globals; no allocation) ----------------
__device__ float  g_qk[(size_t)BB * 128 * NN];        //  19 MB fp32 [q(0:64); k(64:128)][n]
__device__ __half g_qth[(size_t)BB * NN * II];        // 4.7 MB qT hi [n][i]
__device__ __half g_qtl[(size_t)BB * NN * II];        // 4.7 MB qT lo
__device__ __half g_kth[(size_t)BB * NN * II];        // 4.7 MB kT hi [m][i]
__device__ __half g_ktl[(size_t)BB * NN * II];        // 4.7 MB kT lo
__device__ float  g_s[(size_t)BB * NN * NN];          // 324 MB fp32 logits S
__device__ __half g_ph[(size_t)BB * NN * NN];         // 162 MB fp16 softmax P
__device__ __half g_vh[(size_t)BB * CC * NN];         //  36 MB fp16 V
__device__ __half g_xth[(size_t)BB * NN * CC];        //  74 MB fp16 xT [n][c]
__device__ float  g_wqk[128 * CC];                    // [Wq; Wk] concat fp32
__device__ __half g_wvh[CC * CC];                     // Wv fp16

// =====================================================================
// helpers
// =====================================================================
__device__ __forceinline__ uint32_t smem_u32(const void* p) {
    uint32_t a;
    asm("{ .reg .u64 t; cvta.to.shared.u64 t, %1; cvt.u32.u64 %0, t; }"
        : "=r"(a) : "l"(p));
    return a;
}

__device__ __forceinline__ void cp_async16(uint32_t saddr, const void* gptr) {
    asm volatile("cp.async.cg.shared.global [%0], [%1], 16;"
                 :: "r"(saddr), "l"(gptr) : "memory");
}
__device__ __forceinline__ void cp_commit() {
    asm volatile("cp.async.commit_group;" ::: "memory");
}
template<int N>
__device__ __forceinline__ void cp_wait() {
    asm volatile("cp.async.wait_group %0;" :: "n"(N) : "memory");
}

// fp16: D += A(16x16) * B(16x8), fp32 accumulate
__device__ __forceinline__ void mma168816(float* d, const uint32_t* a, const uint32_t* b) {
    asm volatile(
        "mma.sync.aligned.m16n8k16.row.col.f32.f16.f16.f32 "
        "{%0,%1,%2,%3}, {%4,%5,%6,%7}, {%8,%9}, {%0,%1,%2,%3};"
        : "+f"(d[0]), "+f"(d[1]), "+f"(d[2]), "+f"(d[3])
        : "r"(a[0]), "r"(a[1]), "r"(a[2]), "r"(a[3]), "r"(b[0]), "r"(b[1]));
}

// =====================================================================
// prep: concat [Wq;Wk] fp32, convert Wv -> fp16
// =====================================================================
__global__ __launch_bounds__(256)
void prep_w_kernel(const float* __restrict__ Wq, const float* __restrict__ Wk,
                   const float* __restrict__ Wv)
{
    const int i = blockIdx.x * blockDim.x + threadIdx.x;
    if (i < 128 * CC)
        g_wqk[i] = (i < II * CC) ? Wq[i] : Wk[i - II * CC];
    if (i < CC * CC)
        g_wvh[i] = __float2half_rn(Wv[i]);
}

// =====================================================================
// prep: transpose x [c][n] fp32 -> xT [n][c] fp16  (64x64 smem tiles)
// grid (NN/64, CC/64, BB), block 256
// =====================================================================
__global__ __launch_bounds__(256)
void prep_xt_kernel(const float* __restrict__ x)
{
    __shared__ float t[64][65];
    const long long bz = blockIdx.z;
    const int n0 = blockIdx.x * 64;
    const int c0 = blockIdx.y * 64;
    const float* src = x + bz * (long long)(CC * NN);
    __half* dst = g_xth + bz * (long long)(NN * CC);

    const int t4 = threadIdx.x & 3;
    const int r  = threadIdx.x >> 2;     // 0..63

    #pragma unroll
    for (int j = 0; j < 4; j++) {
        float4 v = *(const float4*)(src + (long long)(c0 + r) * NN + n0 + t4 * 16 + j * 4);
        t[r][t4 * 16 + j * 4 + 0] = v.x;
        t[r][t4 * 16 + j * 4 + 1] = v.y;
        t[r][t4 * 16 + j * 4 + 2] = v.z;
        t[r][t4 * 16 + j * 4 + 3] = v.w;
    }
    __syncthreads();

    const long long ob = (long long)(n0 + r) * CC + c0 + t4 * 16;
    #pragma unroll
    for (int w = 0; w < 8; w++) {
        __half2 h = __floats2half2_rn(t[t4 * 16 + 2 * w + 0][r],
                                      t[t4 * 16 + 2 * w + 1][r]);
        *(__half2*)(dst + ob + 2 * w) = h;
    }
}

// =====================================================================
// transpose + fp16 split: qk [i][n] fp32 -> qT/kT [n][i] (hi, lo) fp16
// grid (NN/64, 2, BB), block 256
// =====================================================================
__global__ __launch_bounds__(256)
void tsplit_kernel()
{
    __shared__ float t[64][65];
    const long long bz = blockIdx.z;
    const int n0 = blockIdx.x * 64;
    const bool isq = (blockIdx.y == 0);
    const float* src = g_qk + bz * (long long)(128 * NN) + (isq ? 0 : (long long)II * NN);
    __half* dh = (isq ? g_qth : g_kth) + bz * (long long)(NN * II);
    __half* dl = (isq ? g_qtl : g_ktl) + bz * (long long)(NN * II);

    const int t4 = threadIdx.x & 3;
    const int r  = threadIdx.x >> 2;     // 0..63

    #pragma unroll
    for (int j = 0; j < 4; j++) {
        float4 v = *(const float4*)(src + (long long)r * NN + n0 + t4 * 16 + j * 4);
        t[r][t4 * 16 + j * 4 + 0] = v.x;
        t[r][t4 * 16 + j * 4 + 1] = v.y;
        t[r][t4 * 16 + j * 4 + 2] = v.z;
        t[r][t4 * 16 + j * 4 + 3] = v.w;
    }
    __syncthreads();

    const long long ob = (long long)(n0 + r) * II + t4 * 16;
    #pragma unroll
    for (int w = 0; w < 8; w++) {
        float v0 = t[t4 * 16 + 2 * w + 0][r];
        float v1 = t[t4 * 16 + 2 * w + 1][r];
        __half h0 = __float2half_rn(v0);
        __half h1 = __float2half_rn(v1);
        __half l0 = __float2half_rn(v0 - __half2float(h0));
        __half l1 = __float2half_rn(v1 - __half2float(h1));
        *(__half2*)(dh + ob + 2 * w) = __halves2half2(h0, h1);
        *(__half2*)(dl + ob + 2 * w) = __halves2half2(l0, l1);
    }
}

// =====================================================================
// S[n,m] = sum_i q[i,n]*k[i,m] via split-fp16 mma (round-10 proven)
// =====================================================================
#define SSTR 36
#define STILE (128 * SSTR)
#define S_SMEM (4 * STILE * 4)

__global__ __launch_bounds__(256, 2)
void s_mma_kernel(const __half* __restrict__ qth, const __half* __restrict__ qtl,
                  const __half* __restrict__ kth, const __half* __restrict__ ktl,
                  float* __restrict__ S)
{
    extern __shared__ uint32_t sw[];
    const int tid = threadIdx.x;
    const long long bz = blockIdx.z;
    qth += bz * (long long)(NN * II);
    qtl += bz * (long long)(NN * II);
    kth += bz * (long long)(NN * II);
    ktl += bz * (long long)(NN * II);
    S   += bz * (long long)NN * NN;

    const int n0 = blockIdx.y * 128;
    const int m0 = blockIdx.x * 128;

    {
        const int lr = tid >> 1;
        const int lsg = tid & 1;
        const uint32_t base = smem_u32(sw);
        const uint32_t sd = base + (uint32_t)(lr * SSTR + lsg * 16) * 4u;
        const long long go = (long long)lr * II + lsg * 32;
        const __half* s0 = qth + (long long)n0 * II + go;
        const __half* s1 = qtl + (long long)n0 * II + go;
        const __half* s2 = kth + (long long)m0 * II + go;
        const __half* s3 = ktl + (long long)m0 * II + go;
        #pragma unroll
        for (int c = 0; c < 4; c++) {
            cp_async16(sd + 0 * STILE * 4 + c * 16, s0 + c * 8);
            cp_async16(sd + 1 * STILE * 4 + c * 16, s1 + c * 8);
            cp_async16(sd + 2 * STILE * 4 + c * 16, s2 + c * 8);
            cp_async16(sd + 3 * STILE * 4 + c * 16, s3 + c * 8);
        }
        cp_commit();
    }
    cp_wait<0>();
    __syncthreads();

    const int wid  = tid >> 5, lane = tid & 31;
    const int wm   = (wid >> 2) * 64;
    const int wn   = (wid & 3) * 32;
    const int g4   = lane >> 2;
    const int tg   = lane & 3;

    float acc[4][4][4];
    #pragma unroll
    for (int i = 0; i < 4; i++)
        #pragma unroll
        for (int j = 0; j < 4; j++)
            #pragma unroll
            for (int r = 0; r < 4; r++) acc[i][j][r] = 0.f;

    const uint32_t* QH = sw;
    const uint32_t* QL = sw + STILE;
    const uint32_t* KH = sw + 2 * STILE;
    const uint32_t* KL = sw + 3 * STILE;

    #pragma unroll
    for (int p = 0; p < 3; p++) {
        const uint32_t* A_ = (p == 2) ? QL : QH;
        const uint32_t* B_ = (p == 1) ? KL : KH;
        #pragma unroll
        for (int s = 0; s < 4; s++) {
            const int kw = s * 8 + tg;
            uint32_t a[4][4], b[4][2];
            #pragma unroll
            for (int mt = 0; mt < 4; mt++) {
                const int r0 = wm + mt * 16 + g4;
                a[mt][0] = A_[r0 * SSTR + kw];
                a[mt][1] = A_[(r0 + 8) * SSTR + kw];
                a[mt][2] = A_[r0 * SSTR + kw + 4];
                a[mt][3] = A_[(r0 + 8) * SSTR + kw + 4];
            }
            #pragma unroll
            for (int nt = 0; nt < 4; nt++) {
                const int nr = wn + nt * 8 + g4;
                b[nt][0] = B_[nr * SSTR + kw];
                b[nt][1] = B_[nr * SSTR + kw + 4];
            }
            #pragma unroll
            for (int mt = 0; mt < 4; mt++)
                #pragma unroll
                for (int nt = 0; nt < 4; nt++)
                    mma168816(acc[mt][nt], a[mt], b[nt]);
        }
    }

    #pragma unroll
    for (int mt = 0; mt < 4; mt++) {
        #pragma unroll
        for (int hf = 0; hf < 2; hf++) {
            const int row = n0 + wm + mt * 16 + g4 + hf * 8;
            const long long rb = (long long)row * NN;
            #pragma unroll
            for (int nt = 0; nt < 4; nt++) {
                const int col = m0 + wn + nt * 8 + 2 * tg;
                float2 o;
                o.x = acc[mt][nt][hf * 2 + 0];
                o.y = acc[mt][nt][hf * 2 + 1];
                *(float2*)(S + rb + col) = o;
            }
        }
    }
}

// =====================================================================
// Generic fp16 NT mma kernel: C[m,n] = sum_k A[m,k]*B[n,k], both fp16
// K-contiguous with row stride LD, K = NCH*32.
// EPI=true : Out fp32 = gamma*acc + X.   EPI=false : Out fp16 = acc.
// Out/X row stride NN. CTA tile 128x128, 4-stage cp.async ring. (ov-proven)
// =====================================================================
#define HSTR 20
#define HTILE (128 * HSTR)
#define HSTAGE (2 * HTILE)
#define H_SMEM (4 * HSTAGE * 4)

template<int LD, int NCH, bool EPI>
__global__ __launch_bounds__(256, 2)
void h_nt_mma_kernel(const __half* __restrict__ A, const __half* __restrict__ Bm,
                     const float* __restrict__ X, void* __restrict__ Out,
                     const float* __restrict__ gamma_p,
                     long long sA, long long sB, long long sO)
{
    extern __shared__ uint32_t smw[];

    const int tid = threadIdx.x;
    const long long bz = blockIdx.z;
    A  += bz * sA;
    Bm += bz * sB;
    const float* Xb = X + bz * sO;
    float*  Of = (float*)Out + bz * sO;
    __half* Oh = (__half*)Out + bz * sO;

    const int m0 = blockIdx.y * 128;
    const int n0 = blockIdx.x * 128;

    const int lrow = tid >> 1;
    const int lh   = tid & 1;
    const __half* gA = A  + (long long)(m0 + lrow) * LD + lh * 16;
    const __half* gB = Bm + (long long)(n0 + lrow) * LD + lh * 16;
    const uint32_t sbase = smem_u32(smw);
    const uint32_t sA_st = sbase + (uint32_t)(lrow * HSTR + lh * 8) * 4u;
    const uint32_t sB_st = sA_st + HTILE * 4u;

#define H_ISSUE(c)                                                         \
    do {                                                                   \
        const uint32_t off_ = (uint32_t)((c) & 3) * (HSTAGE * 4u);         \
        const __half* pa_ = gA + (c) * 32;                                 \
        const __half* pb_ = gB + (c) * 32;                                 \
        cp_async16(sA_st + off_,      pa_);                                \
        cp_async16(sA_st + off_ + 16, pa_ + 8);                            \
        cp_async16(sB_st + off_,      pb_);                                \
        cp_async16(sB_st + off_ + 16, pb_ + 8);                            \
        cp_commit();                                                       \
    } while (0)

    H_ISSUE(0); H_ISSUE(1); H_ISSUE(2);

    const int wid  = tid >> 5, lane = tid & 31;
    const int wm   = (wid >> 2) * 64;
    const int wn   = (wid & 3) * 32;
    const int g4   = lane >> 2;
    const int tg   = lane & 3;

    float acc[4][4][4];
    #pragma unroll
    for (int i = 0; i < 4; i++)
        #pragma unroll
        for (int j = 0; j < 4; j++)
            #pragma unroll
            for (int r = 0; r < 4; r++) acc[i][j][r] = 0.f;

    for (int c = 0; c < NCH; c++) {
        if (c + 2 < NCH)       cp_wait<2>();
        else if (c + 1 < NCH)  cp_wait<1>();
        else                   cp_wait<0>();
        __syncthreads();

        if (c + 3 < NCH) H_ISSUE(c + 3);

        const uint32_t* A_ = smw + (c & 3) * HSTAGE;
        const uint32_t* B_ = A_ + HTILE;

        #pragma unroll
        for (int s = 0; s < 2; s++) {
            const int kw = s * 8 + tg;
            uint32_t a[4][4], b[4][2];
            #pragma unroll
            for (int mt = 0; mt < 4; mt++) {
                const int r0 = wm + mt * 16 + g4;
                a[mt][0] = A_[r0 * HSTR + kw];
                a[mt][1] = A_[(r0 + 8) * HSTR + kw];
                a[mt][2] = A_[r0 * HSTR + kw + 4];
                a[mt][3] = A_[(r0 + 8) * HSTR + kw + 4];
            }
            #pragma unroll
            for (int nt = 0; nt < 4; nt++) {
                const int nr = wn + nt * 8 + g4;
                b[nt][0] = B_[nr * HSTR + kw];
                b[nt][1] = B_[nr * HSTR + kw + 4];
            }
            #pragma unroll
            for (int mt = 0; mt < 4; mt++)
                #pragma unroll
                for (int nt = 0; nt < 4; nt++)
                    mma168816(acc[mt][nt], a[mt], b[nt]);
        }
    }

    if (EPI) {
        const float g = *gamma_p;
        #pragma unroll
        for (int mt = 0; mt < 4; mt++) {
            #pragma unroll
            for (int hf = 0; hf < 2; hf++) {
                const int m = m0 + wm + mt * 16 + g4 + hf * 8;
                const long long rb = (long long)m * NN;
                #pragma unroll
                for (int nt = 0; nt < 4; nt++) {
                    const int n = n0 + wn + nt * 8 + 2 * tg;
                    float2 xr = *(const float2*)(Xb + rb + n);
                    float2 o;
                    o.x = fmaf(g, acc[mt][nt][hf * 2 + 0], xr.x);
                    o.y = fmaf(g, acc[mt][nt][hf * 2 + 1], xr.y);
                    *(float2*)(Of + rb + n) = o;
                }
            }
        }
    } else {
        #pragma unroll
        for (int mt = 0; mt < 4; mt++) {
            #pragma unroll
            for (int hf = 0; hf < 2; hf++) {
                const int m = m0 + wm + mt * 16 + g4 + hf * 8;
                const long long rb = (long long)m * NN;
                #pragma unroll
                for (int nt = 0; nt < 4; nt++) {
                    const int n = n0 + wn + nt * 8 + 2 * tg;
                    __half2 h = __floats2half2_rn(acc[mt][nt][hf * 2 + 0],
                                                  acc[mt][nt][hf * 2 + 1]);
                    *(__half2*)(Oh + rb + n) = h;
                }
            }
        }
    }
#undef H_ISSUE
}

// ---------------- generic tiled SGEMM (fp32 SIMT, qk producer) ----------------
static const int TM = 128, TN = 128, TK = 16;

template<bool AK, bool BK, bool EPI>
__global__ __launch_bounds__(256, 2)
void gemm_k(const float* __restrict__ A, const float* __restrict__ Bm,
            float* __restrict__ Cm, int M, int N, int K,
            long long sA, long long sB, long long sC,
            const float* __restrict__ R, long long sR,
            const float* __restrict__ gamma_p)
{
    A  += sA * (long long)blockIdx.z;
    Bm += sB * (long long)blockIdx.z;
    Cm += sC * (long long)blockIdx.z;
    if (EPI) R += sR * (long long)blockIdx.z;

    __shared__ float As[TK][TM];
    __shared__ float Bs[TK][TN];

    const int tid = threadIdx.x;
    const int n0 = blockIdx.x * TN;
    const int m0 = blockIdx.y * TM;
    const int tx = tid & 15;
    const int ty = tid >> 4;

    float acc[8][8];
    #pragma unroll
    for (int i = 0; i < 8; i++)
        #pragma unroll
        for (int j = 0; j < 8; j++) acc[i][j] = 0.f;

    for (int k0 = 0; k0 < K; k0 += TK) {
        if (AK) {
            const int row = tid >> 1;
            const int kc  = (tid & 1) * 8;
            const int m   = m0 + row;
            float4 v0 = make_float4(0.f, 0.f, 0.f, 0.f), v1 = v0;
            if (m < M) {
                const float* p = A + (long long)m * K + k0 + kc;
                v0 = *(const float4*)p;
                v1 = *(const float4*)(p + 4);
            }
            As[kc + 0][row] = v0.x; As[kc + 1][row] = v0.y;
            As[kc + 2][row] = v0.z; As[kc + 3][row] = v0.w;
            As[kc + 4][row] = v1.x; As[kc + 5][row] = v1.y;
            As[kc + 6][row] = v1.z; As[kc + 7][row] = v1.w;
        } else {
            const int kr = tid >> 4;
            const int mc = (tid & 15) * 8;
            const float* p = A + (long long)(k0 + kr) * M + m0 + mc;
            *(float4*)&As[kr][mc]     = *(const float4*)p;
            *(float4*)&As[kr][mc + 4] = *(const float4*)(p + 4);
        }
        if (!BK) {
            const int kr = tid >> 4;
            const int nc = (tid & 15) * 8;
            const float* p = Bm + (long long)(k0 + kr) * N + n0 + nc;
            *(float4*)&Bs[kr][nc]     = *(const float4*)p;
            *(float4*)&Bs[kr][nc + 4] = *(const float4*)(p + 4);
        } else {
            const int row = tid >> 1;
            const int kc  = (tid & 1) * 8;
            const float* p = Bm + (long long)(n0 + row) * K + k0 + kc;
            float4 v0 = *(const float4*)p;
            float4 v1 = *(const float4*)(p + 4);
            Bs[kc + 0][row] = v0.x; Bs[kc + 1][row] = v0.y;
            Bs[kc + 2][row] = v0.z; Bs[kc + 3][row] = v0.w;
            Bs[kc + 4][row] = v1.x; Bs[kc + 5][row] = v1.y;
            Bs[kc + 6][row] = v1.z; Bs[kc + 7][row] = v1.w;
        }
        __syncthreads();

        #pragma unroll
        for (int kk = 0; kk < TK; kk++) {
            float a[8], b[8];
            *(float4*)(a)     = *(const float4*)&As[kk][ty * 8];
            *(float4*)(a + 4) = *(const float4*)&As[kk][ty * 8 + 4];
            *(float4*)(b)     = *(const float4*)&Bs[kk][tx * 8];
            *(float4*)(b + 4) = *(const float4*)&Bs[kk][tx * 8 + 4];
            #pragma unroll
            for (int i = 0; i < 8; i++)
                #pragma unroll
                for (int j = 0; j < 8; j++)
                    acc[i][j] = fmaf(a[i], b[j], acc[i][j]);
        }
        __syncthreads();
    }

    const float g = EPI ? *gamma_p : 0.f;
    #pragma unroll
    for (int i = 0; i < 8; i++) {
        const int m = m0 + ty * 8 + i;
        if (m < M) {
            float* dst = Cm + (long long)m * N + n0 + tx * 8;
            if (EPI) {
                const float* r = R + (long long)m * N + n0 + tx * 8;
                float4 r0 = *(const float4*)r;
                float4 r1 = *(const float4*)(r + 4);
                float4 o0, o1;
                o0.x = fmaf(g, acc[i][0], r0.x); o0.y = fmaf(g, acc[i][1], r0.y);
                o0.z = fmaf(g, acc[i][2], r0.z); o0.w = fmaf(g, acc[i][3], r0.w);
                o1.x = fmaf(g, acc[i][4], r1.x); o1.y = fmaf(g, acc[i][5], r1.y);
                o1.z = fmaf(g, acc[i][6], r1.z); o1.w = fmaf(g, acc[i][7], r1.w);
                *(float4*)dst       = o0;
                *(float4*)(dst + 4) = o1;
            } else {
                float4 o0 = make_float4(acc[i][0], acc[i][1], acc[i][2], acc[i][3]);
                float4 o1 = make_float4(acc[i][4], acc[i][5], acc[i][6], acc[i][7]);
                *(float4*)dst       = o0;
                *(float4*)(dst + 4) = o1;
            }
        }
    }
}

// ---------------- row softmax; reads fp32 S, writes fp16 P ----------------
__global__ __launch_bounds__(256)
void softmax_rows(const float* __restrict__ S, __half* __restrict__ P)
{
    __shared__ float red[8];
    const float* p = S + (size_t)blockIdx.x * NN;
    __half*      o = P + (size_t)blockIdx.x * NN;
    const int tid  = threadIdx.x;
    const int lane = tid & 31;
    const int wid  = tid >> 5;

    float v[9];
    float m = -1e30f;
    #pragma unroll
    for (int j = 0; j < 9; j++) {
        v[j] = p[tid + 256 * j];
        m = fmaxf(m, v[j]);
    }
    #pragma unroll
    for (int ofs = 16; ofs; ofs >>= 1) m = fmaxf(m, __shfl_xor_sync(0xffffffffu, m, ofs));
    if (lane == 0) red[wid] = m;
    __syncthreads();
    m = red[0];
    #pragma unroll
    for (int i = 1; i < 8; i++) m = fmaxf(m, red[i]);
    __syncthreads();

    float s = 0.f;
    #pragma unroll
    for (int j = 0; j < 9; j++) {
        v[j] = expf(v[j] - m);
        s += v[j];
    }
    #pragma unroll
    for (int ofs = 16; ofs; ofs >>= 1) s += __shfl_xor_sync(0xffffffffu, s, ofs);
    if (lane == 0) red[wid] = s;
    __syncthreads();
    s = 0.f;
    #pragma unroll
    for (int i = 0; i < 8; i++) s += red[i];

    const float inv = 1.f / s;
    #pragma unroll
    for (int j = 0; j < 9; j++)
        o[tid + 256 * j] = __float2half_rn(v[j] * inv);
}

// ---------------- launch ----------------
extern "C" void kernel_launch(void* const* d_in, const int* in_sizes, int n_in,
                              void* d_out, int out_size)
{
    const float* x     = (const float*)d_in[0];   // (16,512,48,48)
    const float* Wq    = (const float*)d_in[1];   // (64,512)
    const float* Wk    = (const float*)d_in[2];   // (64,512)
    const float* Wv    = (const float*)d_in[3];   // (512,512)
    const float* gamma = (const float*)d_in[4];   // (1,)
    float* out = (float*)d_out;

    float *qk, *s, *wqk;
    __half *ph, *vh, *qth, *qtl, *kth, *ktl, *xth, *wvh;
    cudaGetSymbolAddress((void**)&qk,  g_qk);
    cudaGetSymbolAddress((void**)&s,   g_s);
    cudaGetSymbolAddress((void**)&wqk, g_wqk);
    cudaGetSymbolAddress((void**)&ph,  g_ph);
    cudaGetSymbolAddress((void**)&vh,  g_vh);
    cudaGetSymbolAddress((void**)&qth, g_qth);
    cudaGetSymbolAddress((void**)&qtl, g_qtl);
    cudaGetSymbolAddress((void**)&kth, g_kth);
    cudaGetSymbolAddress((void**)&ktl, g_ktl);
    cudaGetSymbolAddress((void**)&xth, g_xth);
    cudaGetSymbolAddress((void**)&wvh, g_wvh);

    const long long sX = (long long)CC * NN;

    dim3 blk(256);

    // prep: [Wq;Wk] concat, Wv->fp16; x -> xT fp16
    prep_w_kernel<<<(CC * CC + 255) / 256, 256>>>(Wq, Wk, Wv);
    prep_xt_kernel<<<dim3(NN / 64, CC / 64, BB), blk>>>(x);

    // [q; k] = [Wq; Wk] @ x : one fused fp32 SIMT launch, M=128
    gemm_k<true, false, false><<<dim3(NN / TN, 1, BB), blk>>>(
        wqk, x, qk, 128, NN, CC, 0, sX, (long long)128 * NN, nullptr, 0, nullptr);

    // v = Wv @ xT : fp16 mma (same operand mantissa as prior tf32 path)
    cudaFuncSetAttribute(h_nt_mma_kernel<CC, CC / 32, false>,
                         cudaFuncAttributeMaxDynamicSharedMemorySize, H_SMEM);
    h_nt_mma_kernel<CC, CC / 32, false><<<dim3(NN / 128, CC / 128, BB), blk, H_SMEM>>>(
        wvh, xth, nullptr, vh, nullptr, 0, (long long)NN * CC, sX);

    // transpose + fp16 split of q, k
    tsplit_kernel<<<dim3(NN / 64, 2, BB), blk>>>();

    // S = q^T @ k  (split-fp16 mma, fp32-grade accuracy)
    cudaFuncSetAttribute(s_mma_kernel,
                         cudaFuncAttributeMaxDynamicSharedMemorySize, S_SMEM);
    s_mma_kernel<<<dim3(NN / 128, NN / 128, BB), blk, S_SMEM>>>(
        qth, qtl, kth, ktl, s);

    // P = softmax(S), emitted fp16
    softmax_rows<<<BB * NN, 256>>>(s, ph);

    // out = gamma * (V @ P^T) + x  (fp16 mma, fp32 accumulate)
    cudaFuncSetAttribute(h_nt_mma_kernel<NN, NN / 32, true>,
                         cudaFuncAttributeMaxDynamicSharedMemorySize, H_SMEM);
    h_nt_mma_kernel<NN, NN / 32, true><<<dim3(NN / 128, CC / 128, BB), blk, H_SMEM>>>(
        vh, ph, x, out, gamma, sX, (long long)NN * NN, sX);
}

// round 13
// speedup vs baseline: 2.5275x; 1.0167x over previous
#include <cuda_runtime.h>
#include <cuda_fp16.h>
#include <stdint.h>
#include <math.h>

// Problem constants
#define BB 16
#define CC 512
#define NN 2304      // 48*48
#define II 64

// ---------------- scratch (static device globals; no allocation) ----------------
__device__ float  g_qk[(size_t)BB * 128 * NN];        //  19 MB fp32 [q(0:64); k(64:128)][n]
__device__ __half g_qth[(size_t)BB * NN * II];        // 4.7 MB qT hi [n][i]
__device__ __half g_qtl[(size_t)BB * NN * II];        // 4.7 MB qT lo
__device__ __half g_kth[(size_t)BB * NN * II];        // 4.7 MB kT hi [m][i]
__device__ __half g_ktl[(size_t)BB * NN * II];        // 4.7 MB kT lo
__device__ float  g_s[(size_t)BB * NN * NN];          // 324 MB fp32 logits S
__device__ __half g_ph[(size_t)BB * NN * NN];         // 162 MB fp16 softmax P
__device__ __half g_vh[(size_t)BB * CC * NN];         //  36 MB fp16 V
__device__ __half g_xth[(size_t)BB * NN * CC];        //  74 MB fp16 xT [n][c]
__device__ float  g_wqk[128 * CC];                    // [Wq; Wk] concat fp32
__device__ __half g_wvh[CC * CC];                     // Wv fp16

// =====================================================================
// helpers
// =====================================================================
__device__ __forceinline__ uint32_t smem_u32(const void* p) {
    uint32_t a;
    asm("{ .reg .u64 t; cvta.to.shared.u64 t, %1; cvt.u32.u64 %0, t; }"
        : "=r"(a) : "l"(p));
    return a;
}

__device__ __forceinline__ void cp_async16(uint32_t saddr, const void* gptr) {
    asm volatile("cp.async.cg.shared.global [%0], [%1], 16;"
                 :: "r"(saddr), "l"(gptr) : "memory");
}
__device__ __forceinline__ void cp_commit() {
    asm volatile("cp.async.commit_group;" ::: "memory");
}
template<int N>
__device__ __forceinline__ void cp_wait() {
    asm volatile("cp.async.wait_group %0;" :: "n"(N) : "memory");
}

// fp16: D += A(16x16) * B(16x8), fp32 accumulate
__device__ __forceinline__ void mma168816(float* d, const uint32_t* a, const uint32_t* b) {
    asm volatile(
        "mma.sync.aligned.m16n8k16.row.col.f32.f16.f16.f32 "
        "{%0,%1,%2,%3}, {%4,%5,%6,%7}, {%8,%9}, {%0,%1,%2,%3};"
        : "+f"(d[0]), "+f"(d[1]), "+f"(d[2]), "+f"(d[3])
        : "r"(a[0]), "r"(a[1]), "r"(a[2]), "r"(a[3]), "r"(b[0]), "r"(b[1]));
}

// ldmatrix: 4x / 2x 8x8 b16 matrices from shared
__device__ __forceinline__ void ldsm_x4(uint32_t* r, uint32_t addr) {
    asm volatile("ldmatrix.sync.aligned.m8n8.x4.shared.b16 {%0,%1,%2,%3}, [%4];"
                 : "=r"(r[0]), "=r"(r[1]), "=r"(r[2]), "=r"(r[3]) : "r"(addr));
}
__device__ __forceinline__ void ldsm_x2(uint32_t* r, uint32_t addr) {
    asm volatile("ldmatrix.sync.aligned.m8n8.x2.shared.b16 {%0,%1}, [%2];"
                 : "=r"(r[0]), "=r"(r[1]) : "r"(addr));
}

// =====================================================================
// prep: concat [Wq;Wk] fp32, convert Wv -> fp16
// =====================================================================
__global__ __launch_bounds__(256)
void prep_w_kernel(const float* __restrict__ Wq, const float* __restrict__ Wk,
                   const float* __restrict__ Wv)
{
    const int i = blockIdx.x * blockDim.x + threadIdx.x;
    if (i < 128 * CC)
        g_wqk[i] = (i < II * CC) ? Wq[i] : Wk[i - II * CC];
    if (i < CC * CC)
        g_wvh[i] = __float2half_rn(Wv[i]);
}

// =====================================================================
// prep: transpose x [c][n] fp32 -> xT [n][c] fp16  (64x64 smem tiles)
// =====================================================================
__global__ __launch_bounds__(256)
void prep_xt_kernel(const float* __restrict__ x)
{
    __shared__ float t[64][65];
    const long long bz = blockIdx.z;
    const int n0 = blockIdx.x * 64;
    const int c0 = blockIdx.y * 64;
    const float* src = x + bz * (long long)(CC * NN);
    __half* dst = g_xth + bz * (long long)(NN * CC);

    const int t4 = threadIdx.x & 3;
    const int r  = threadIdx.x >> 2;     // 0..63

    #pragma unroll
    for (int j = 0; j < 4; j++) {
        float4 v = *(const float4*)(src + (long long)(c0 + r) * NN + n0 + t4 * 16 + j * 4);
        t[r][t4 * 16 + j * 4 + 0] = v.x;
        t[r][t4 * 16 + j * 4 + 1] = v.y;
        t[r][t4 * 16 + j * 4 + 2] = v.z;
        t[r][t4 * 16 + j * 4 + 3] = v.w;
    }
    __syncthreads();

    const long long ob = (long long)(n0 + r) * CC + c0 + t4 * 16;
    #pragma unroll
    for (int w = 0; w < 8; w++) {
        __half2 h = __floats2half2_rn(t[t4 * 16 + 2 * w + 0][r],
                                      t[t4 * 16 + 2 * w + 1][r]);
        *(__half2*)(dst + ob + 2 * w) = h;
    }
}

// =====================================================================
// transpose + fp16 split: qk [i][n] fp32 -> qT/kT [n][i] (hi, lo) fp16
// =====================================================================
__global__ __launch_bounds__(256)
void tsplit_kernel()
{
    __shared__ float t[64][65];
    const long long bz = blockIdx.z;
    const int n0 = blockIdx.x * 64;
    const bool isq = (blockIdx.y == 0);
    const float* src = g_qk + bz * (long long)(128 * NN) + (isq ? 0 : (long long)II * NN);
    __half* dh = (isq ? g_qth : g_kth) + bz * (long long)(NN * II);
    __half* dl = (isq ? g_qtl : g_ktl) + bz * (long long)(NN * II);

    const int t4 = threadIdx.x & 3;
    const int r  = threadIdx.x >> 2;     // 0..63

    #pragma unroll
    for (int j = 0; j < 4; j++) {
        float4 v = *(const float4*)(src + (long long)r * NN + n0 + t4 * 16 + j * 4);
        t[r][t4 * 16 + j * 4 + 0] = v.x;
        t[r][t4 * 16 + j * 4 + 1] = v.y;
        t[r][t4 * 16 + j * 4 + 2] = v.z;
        t[r][t4 * 16 + j * 4 + 3] = v.w;
    }
    __syncthreads();

    const long long ob = (long long)(n0 + r) * II + t4 * 16;
    #pragma unroll
    for (int w = 0; w < 8; w++) {
        float v0 = t[t4 * 16 + 2 * w + 0][r];
        float v1 = t[t4 * 16 + 2 * w + 1][r];
        __half h0 = __float2half_rn(v0);
        __half h1 = __float2half_rn(v1);
        __half l0 = __float2half_rn(v0 - __half2float(h0));
        __half l1 = __float2half_rn(v1 - __half2float(h1));
        *(__half2*)(dh + ob + 2 * w) = __halves2half2(h0, h1);
        *(__half2*)(dl + ob + 2 * w) = __halves2half2(l0, l1);
    }
}

// =====================================================================
// S[n,m] = sum_i q[i,n]*k[i,m] via split-fp16 mma (round-10 proven)
// =====================================================================
#define SSTR 36
#define STILE (128 * SSTR)
#define S_SMEM (4 * STILE * 4)

__global__ __launch_bounds__(256, 2)
void s_mma_kernel(const __half* __restrict__ qth, const __half* __restrict__ qtl,
                  const __half* __restrict__ kth, const __half* __restrict__ ktl,
                  float* __restrict__ S)
{
    extern __shared__ uint32_t sw[];
    const int tid = threadIdx.x;
    const long long bz = blockIdx.z;
    qth += bz * (long long)(NN * II);
    qtl += bz * (long long)(NN * II);
    kth += bz * (long long)(NN * II);
    ktl += bz * (long long)(NN * II);
    S   += bz * (long long)NN * NN;

    const int n0 = blockIdx.y * 128;
    const int m0 = blockIdx.x * 128;

    {
        const int lr = tid >> 1;
        const int lsg = tid & 1;
        const uint32_t base = smem_u32(sw);
        const uint32_t sd = base + (uint32_t)(lr * SSTR + lsg * 16) * 4u;
        const long long go = (long long)lr * II + lsg * 32;
        const __half* s0 = qth + (long long)n0 * II + go;
        const __half* s1 = qtl + (long long)n0 * II + go;
        const __half* s2 = kth + (long long)m0 * II + go;
        const __half* s3 = ktl + (long long)m0 * II + go;
        #pragma unroll
        for (int c = 0; c < 4; c++) {
            cp_async16(sd + 0 * STILE * 4 + c * 16, s0 + c * 8);
            cp_async16(sd + 1 * STILE * 4 + c * 16, s1 + c * 8);
            cp_async16(sd + 2 * STILE * 4 + c * 16, s2 + c * 8);
            cp_async16(sd + 3 * STILE * 4 + c * 16, s3 + c * 8);
        }
        cp_commit();
    }
    cp_wait<0>();
    __syncthreads();

    const int wid  = tid >> 5, lane = tid & 31;
    const int wm   = (wid >> 2) * 64;
    const int wn   = (wid & 3) * 32;
    const int g4   = lane >> 2;
    const int tg   = lane & 3;

    float acc[4][4][4];
    #pragma unroll
    for (int i = 0; i < 4; i++)
        #pragma unroll
        for (int j = 0; j < 4; j++)
            #pragma unroll
            for (int r = 0; r < 4; r++) acc[i][j][r] = 0.f;

    const uint32_t* QH = sw;
    const uint32_t* QL = sw + STILE;
    const uint32_t* KH = sw + 2 * STILE;
    const uint32_t* KL = sw + 3 * STILE;

    #pragma unroll
    for (int p = 0; p < 3; p++) {
        const uint32_t* A_ = (p == 2) ? QL : QH;
        const uint32_t* B_ = (p == 1) ? KL : KH;
        #pragma unroll
        for (int s = 0; s < 4; s++) {
            const int kw = s * 8 + tg;
            uint32_t a[4][4], b[4][2];
            #pragma unroll
            for (int mt = 0; mt < 4; mt++) {
                const int r0 = wm + mt * 16 + g4;
                a[mt][0] = A_[r0 * SSTR + kw];
                a[mt][1] = A_[(r0 + 8) * SSTR + kw];
                a[mt][2] = A_[r0 * SSTR + kw + 4];
                a[mt][3] = A_[(r0 + 8) * SSTR + kw + 4];
            }
            #pragma unroll
            for (int nt = 0; nt < 4; nt++) {
                const int nr = wn + nt * 8 + g4;
                b[nt][0] = B_[nr * SSTR + kw];
                b[nt][1] = B_[nr * SSTR + kw + 4];
            }
            #pragma unroll
            for (int mt = 0; mt < 4; mt++)
                #pragma unroll
                for (int nt = 0; nt < 4; nt++)
                    mma168816(acc[mt][nt], a[mt], b[nt]);
        }
    }

    #pragma unroll
    for (int mt = 0; mt < 4; mt++) {
        #pragma unroll
        for (int hf = 0; hf < 2; hf++) {
            const int row = n0 + wm + mt * 16 + g4 + hf * 8;
            const long long rb = (long long)row * NN;
            #pragma unroll
            for (int nt = 0; nt < 4; nt++) {
                const int col = m0 + wn + nt * 8 + 2 * tg;
                float2 o;
                o.x = acc[mt][nt][hf * 2 + 0];
                o.y = acc[mt][nt][hf * 2 + 1];
                *(float2*)(S + rb + col) = o;
            }
        }
    }
}

// =====================================================================
// Generic fp16 NT mma kernel: C[m,n] = sum_k A[m,k]*B[n,k], both fp16
// K-contiguous with row stride LD, K = NCH*32.
// Fragments now loaded via ldmatrix (x4 for A, x2 for B) — identical
// lane mapping to the previous manual LDS loads, 3x fewer instructions.
// =====================================================================
#define HSTR 20
#define HTILE (128 * HSTR)
#define HSTAGE (2 * HTILE)
#define H_SMEM (4 * HSTAGE * 4)

template<int LD, int NCH, bool EPI>
__global__ __launch_bounds__(256, 2)
void h_nt_mma_kernel(const __half* __restrict__ A, const __half* __restrict__ Bm,
                     const float* __restrict__ X, void* __restrict__ Out,
                     const float* __restrict__ gamma_p,
                     long long sA, long long sB, long long sO)
{
    extern __shared__ uint32_t smw[];

    const int tid = threadIdx.x;
    const long long bz = blockIdx.z;
    A  += bz * sA;
    Bm += bz * sB;
    const float* Xb = X + bz * sO;
    float*  Of = (float*)Out + bz * sO;
    __half* Oh = (__half*)Out + bz * sO;

    const int m0 = blockIdx.y * 128;
    const int n0 = blockIdx.x * 128;

    const int lrow = tid >> 1;
    const int lh   = tid & 1;
    const __half* gA = A  + (long long)(m0 + lrow) * LD + lh * 16;
    const __half* gB = Bm + (long long)(n0 + lrow) * LD + lh * 16;
    const uint32_t sbase = smem_u32(smw);
    const uint32_t sA_st = sbase + (uint32_t)(lrow * HSTR + lh * 8) * 4u;
    const uint32_t sB_st = sA_st + HTILE * 4u;

#define H_ISSUE(c)                                                         \
    do {                                                                   \
        const uint32_t off_ = (uint32_t)((c) & 3) * (HSTAGE * 4u);         \
        const __half* pa_ = gA + (c) * 32;                                 \
        const __half* pb_ = gB + (c) * 32;                                 \
        cp_async16(sA_st + off_,      pa_);                                \
        cp_async16(sA_st + off_ + 16, pa_ + 8);                            \
        cp_async16(sB_st + off_,      pb_);                                \
        cp_async16(sB_st + off_ + 16, pb_ + 8);                            \
        cp_commit();                                                       \
    } while (0)

    H_ISSUE(0); H_ISSUE(1); H_ISSUE(2);

    const int wid  = tid >> 5, lane = tid & 31;
    const int wm   = (wid >> 2) * 64;
    const int wn   = (wid & 3) * 32;
    const int g4   = lane >> 2;
    const int tg   = lane & 3;

    // ldmatrix lane addresses (byte offsets within a stage)
    //  A x4: matrices {m0-7 k0-7, m8-15 k0-7, m0-7 k8-15, m8-15 k8-15}
    //        lane l -> row wm+mt*16+(l&15), word (l>>4)*4
    //  B x2: matrices {n0-7 k0-7, n0-7 k8-15}
    //        lane l -> row wn+nt*8+(l&7), word ((l>>3)&1)*4
    uint32_t aAddr[4], bAddr[4];
    #pragma unroll
    for (int mt = 0; mt < 4; mt++)
        aAddr[mt] = sbase +
            (uint32_t)((wm + mt * 16 + (lane & 15)) * HSTR + (lane >> 4) * 4) * 4u;
    #pragma unroll
    for (int nt = 0; nt < 4; nt++)
        bAddr[nt] = sbase +
            (uint32_t)(HTILE + (wn + nt * 8 + (lane & 7)) * HSTR + ((lane >> 3) & 1) * 4) * 4u;

    float acc[4][4][4];
    #pragma unroll
    for (int i = 0; i < 4; i++)
        #pragma unroll
        for (int j = 0; j < 4; j++)
            #pragma unroll
            for (int r = 0; r < 4; r++) acc[i][j][r] = 0.f;

    for (int c = 0; c < NCH; c++) {
        if (c + 2 < NCH)       cp_wait<2>();
        else if (c + 1 < NCH)  cp_wait<1>();
        else                   cp_wait<0>();
        __syncthreads();

        if (c + 3 < NCH) H_ISSUE(c + 3);

        const uint32_t so = (uint32_t)(c & 3) * (HSTAGE * 4u);

        #pragma unroll
        for (int s = 0; s < 2; s++) {
            const uint32_t ko = so + (uint32_t)s * 32u;   // s*8 words
            uint32_t a[4][4], b[4][2];
            #pragma unroll
            for (int mt = 0; mt < 4; mt++)
                ldsm_x4(a[mt], aAddr[mt] + ko);
            #pragma unroll
            for (int nt = 0; nt < 4; nt++)
                ldsm_x2(b[nt], bAddr[nt] + ko);
            #pragma unroll
            for (int mt = 0; mt < 4; mt++)
                #pragma unroll
                for (int nt = 0; nt < 4; nt++)
                    mma168816(acc[mt][nt], a[mt], b[nt]);
        }
    }

    if (EPI) {
        const float g = *gamma_p;
        #pragma unroll
        for (int mt = 0; mt < 4; mt++) {
            #pragma unroll
            for (int hf = 0; hf < 2; hf++) {
                const int m = m0 + wm + mt * 16 + g4 + hf * 8;
                const long long rb = (long long)m * NN;
                #pragma unroll
                for (int nt = 0; nt < 4; nt++) {
                    const int n = n0 + wn + nt * 8 + 2 * tg;
                    float2 xr = *(const float2*)(Xb + rb + n);
                    float2 o;
                    o.x = fmaf(g, acc[mt][nt][hf * 2 + 0], xr.x);
                    o.y = fmaf(g, acc[mt][nt][hf * 2 + 1], xr.y);
                    *(float2*)(Of + rb + n) = o;
                }
            }
        }
    } else {
        #pragma unroll
        for (int mt = 0; mt < 4; mt++) {
            #pragma unroll
            for (int hf = 0; hf < 2; hf++) {
                const int m = m0 + wm + mt * 16 + g4 + hf * 8;
                const long long rb = (long long)m * NN;
                #pragma unroll
                for (int nt = 0; nt < 4; nt++) {
                    const int n = n0 + wn + nt * 8 + 2 * tg;
                    __half2 h = __floats2half2_rn(acc[mt][nt][hf * 2 + 0],
                                                  acc[mt][nt][hf * 2 + 1]);
                    *(__half2*)(Oh + rb + n) = h;
                }
            }
        }
    }
#undef H_ISSUE
}

// ---------------- generic tiled SGEMM (fp32 SIMT, qk producer) ----------------
static const int TM = 128, TN = 128, TK = 16;

template<bool AK, bool BK, bool EPI>
__global__ __launch_bounds__(256, 2)
void gemm_k(const float* __restrict__ A, const float* __restrict__ Bm,
            float* __restrict__ Cm, int M, int N, int K,
            long long sA, long long sB, long long sC,
            const float* __restrict__ R, long long sR,
            const float* __restrict__ gamma_p)
{
    A  += sA * (long long)blockIdx.z;
    Bm += sB * (long long)blockIdx.z;
    Cm += sC * (long long)blockIdx.z;
    if (EPI) R += sR * (long long)blockIdx.z;

    __shared__ float As[TK][TM];
    __shared__ float Bs[TK][TN];

    const int tid = threadIdx.x;
    const int n0 = blockIdx.x * TN;
    const int m0 = blockIdx.y * TM;
    const int tx = tid & 15;
    const int ty = tid >> 4;

    float acc[8][8];
    #pragma unroll
    for (int i = 0; i < 8; i++)
        #pragma unroll
        for (int j = 0; j < 8; j++) acc[i][j] = 0.f;

    for (int k0 = 0; k0 < K; k0 += TK) {
        if (AK) {
            const int row = tid >> 1;
            const int kc  = (tid & 1) * 8;
            const int m   = m0 + row;
            float4 v0 = make_float4(0.f, 0.f, 0.f, 0.f), v1 = v0;
            if (m < M) {
                const float* p = A + (long long)m * K + k0 + kc;
                v0 = *(const float4*)p;
                v1 = *(const float4*)(p + 4);
            }
            As[kc + 0][row] = v0.x; As[kc + 1][row] = v0.y;
            As[kc + 2][row] = v0.z; As[kc + 3][row] = v0.w;
            As[kc + 4][row] = v1.x; As[kc + 5][row] = v1.y;
            As[kc + 6][row] = v1.z; As[kc + 7][row] = v1.w;
        } else {
            const int kr = tid >> 4;
            const int mc = (tid & 15) * 8;
            const float* p = A + (long long)(k0 + kr) * M + m0 + mc;
            *(float4*)&As[kr][mc]     = *(const float4*)p;
            *(float4*)&As[kr][mc + 4] = *(const float4*)(p + 4);
        }
        if (!BK) {
            const int kr = tid >> 4;
            const int nc = (tid & 15) * 8;
            const float* p = Bm + (long long)(k0 + kr) * N + n0 + nc;
            *(float4*)&Bs[kr][nc]     = *(const float4*)p;
            *(float4*)&Bs[kr][nc + 4] = *(const float4*)(p + 4);
        } else {
            const int row = tid >> 1;
            const int kc  = (tid & 1) * 8;
            const float* p = Bm + (long long)(n0 + row) * K + k0 + kc;
            float4 v0 = *(const float4*)p;
            float4 v1 = *(const float4*)(p + 4);
            Bs[kc + 0][row] = v0.x; Bs[kc + 1][row] = v0.y;
            Bs[kc + 2][row] = v0.z; Bs[kc + 3][row] = v0.w;
            Bs[kc + 4][row] = v1.x; Bs[kc + 5][row] = v1.y;
            Bs[kc + 6][row] = v1.z; Bs[kc + 7][row] = v1.w;
        }
        __syncthreads();

        #pragma unroll
        for (int kk = 0; kk < TK; kk++) {
            float a[8], b[8];
            *(float4*)(a)     = *(const float4*)&As[kk][ty * 8];
            *(float4*)(a + 4) = *(const float4*)&As[kk][ty * 8 + 4];
            *(float4*)(b)     = *(const float4*)&Bs[kk][tx * 8];
            *(float4*)(b + 4) = *(const float4*)&Bs[kk][tx * 8 + 4];
            #pragma unroll
            for (int i = 0; i < 8; i++)
                #pragma unroll
                for (int j = 0; j < 8; j++)
                    acc[i][j] = fmaf(a[i], b[j], acc[i][j]);
        }
        __syncthreads();
    }

    const float g = EPI ? *gamma_p : 0.f;
    #pragma unroll
    for (int i = 0; i < 8; i++) {
        const int m = m0 + ty * 8 + i;
        if (m < M) {
            float* dst = Cm + (long long)m * N + n0 + tx * 8;
            if (EPI) {
                const float* r = R + (long long)m * N + n0 + tx * 8;
                float4 r0 = *(const float4*)r;
                float4 r1 = *(const float4*)(r + 4);
                float4 o0, o1;
                o0.x = fmaf(g, acc[i][0], r0.x); o0.y = fmaf(g, acc[i][1], r0.y);
                o0.z = fmaf(g, acc[i][2], r0.z); o0.w = fmaf(g, acc[i][3], r0.w);
                o1.x = fmaf(g, acc[i][4], r1.x); o1.y = fmaf(g, acc[i][5], r1.y);
                o1.z = fmaf(g, acc[i][6], r1.z); o1.w = fmaf(g, acc[i][7], r1.w);
                *(float4*)dst       = o0;
                *(float4*)(dst + 4) = o1;
            } else {
                float4 o0 = make_float4(acc[i][0], acc[i][1], acc[i][2], acc[i][3]);
                float4 o1 = make_float4(acc[i][4], acc[i][5], acc[i][6], acc[i][7]);
                *(float4*)dst       = o0;
                *(float4*)(dst + 4) = o1;
            }
        }
    }
}

// ---------------- row softmax; reads fp32 S, writes fp16 P ----------------
__global__ __launch_bounds__(256)
void softmax_rows(const float* __restrict__ S, __half* __restrict__ P)
{
    __shared__ float red[8];
    const float* p = S + (size_t)blockIdx.x * NN;
    __half*      o = P + (size_t)blockIdx.x * NN;
    const int tid  = threadIdx.x;
    const int lane = tid & 31;
    const int wid  = tid >> 5;

    float v[9];
    float m = -1e30f;
    #pragma unroll
    for (int j = 0; j < 9; j++) {
        v[j] = p[tid + 256 * j];
        m = fmaxf(m, v[j]);
    }
    #pragma unroll
    for (int ofs = 16; ofs; ofs >>= 1) m = fmaxf(m, __shfl_xor_sync(0xffffffffu, m, ofs));
    if (lane == 0) red[wid] = m;
    __syncthreads();
    m = red[0];
    #pragma unroll
    for (int i = 1; i < 8; i++) m = fmaxf(m, red[i]);
    __syncthreads();

    float s = 0.f;
    #pragma unroll
    for (int j = 0; j < 9; j++) {
        v[j] = expf(v[j] - m);
        s += v[j];
    }
    #pragma unroll
    for (int ofs = 16; ofs; ofs >>= 1) s += __shfl_xor_sync(0xffffffffu, s, ofs);
    if (lane == 0) red[wid] = s;
    __syncthreads();
    s = 0.f;
    #pragma unroll
    for (int i = 0; i < 8; i++) s += red[i];

    const float inv = 1.f / s;
    #pragma unroll
    for (int j = 0; j < 9; j++)
        o[tid + 256 * j] = __float2half_rn(v[j] * inv);
}

// ---------------- launch ----------------
extern "C" void kernel_launch(void* const* d_in, const int* in_sizes, int n_in,
                              void* d_out, int out_size)
{
    const float* x     = (const float*)d_in[0];   // (16,512,48,48)
    const float* Wq    = (const float*)d_in[1];   // (64,512)
    const float* Wk    = (const float*)d_in[2];   // (64,512)
    const float* Wv    = (const float*)d_in[3];   // (512,512)
    const float* gamma = (const float*)d_in[4];   // (1,)
    float* out = (float*)d_out;

    float *qk, *s, *wqk;
    __half *ph, *vh, *qth, *qtl, *kth, *ktl, *xth, *wvh;
    cudaGetSymbolAddress((void**)&qk,  g_qk);
    cudaGetSymbolAddress((void**)&s,   g_s);
    cudaGetSymbolAddress((void**)&wqk, g_wqk);
    cudaGetSymbolAddress((void**)&ph,  g_ph);
    cudaGetSymbolAddress((void**)&vh,  g_vh);
    cudaGetSymbolAddress((void**)&qth, g_qth);
    cudaGetSymbolAddress((void**)&qtl, g_qtl);
    cudaGetSymbolAddress((void**)&kth, g_kth);
    cudaGetSymbolAddress((void**)&ktl, g_ktl);
    cudaGetSymbolAddress((void**)&xth, g_xth);
    cudaGetSymbolAddress((void**)&wvh, g_wvh);

    const long long sX = (long long)CC * NN;

    dim3 blk(256);

    // prep: [Wq;Wk] concat, Wv->fp16; x -> xT fp16
    prep_w_kernel<<<(CC * CC + 255) / 256, 256>>>(Wq, Wk, Wv);
    prep_xt_kernel<<<dim3(NN / 64, CC / 64, BB), blk>>>(x);

    // [q; k] = [Wq; Wk] @ x : one fused fp32 SIMT launch, M=128
    gemm_k<true, false, false><<<dim3(NN / TN, 1, BB), blk>>>(
        wqk, x, qk, 128, NN, CC, 0, sX, (long long)128 * NN, nullptr, 0, nullptr);

    // v = Wv @ xT : fp16 mma (ldmatrix fragments)
    cudaFuncSetAttribute(h_nt_mma_kernel<CC, CC / 32, false>,
                         cudaFuncAttributeMaxDynamicSharedMemorySize, H_SMEM);
    h_nt_mma_kernel<CC, CC / 32, false><<<dim3(NN / 128, CC / 128, BB), blk, H_SMEM>>>(
        wvh, xth, nullptr, vh, nullptr, 0, (long long)NN * CC, sX);

    // transpose + fp16 split of q, k
    tsplit_kernel<<<dim3(NN / 64, 2, BB), blk>>>();

    // S = q^T @ k  (split-fp16 mma, fp32-grade accuracy)
    cudaFuncSetAttribute(s_mma_kernel,
                         cudaFuncAttributeMaxDynamicSharedMemorySize, S_SMEM);
    s_mma_kernel<<<dim3(NN / 128, NN / 128, BB), blk, S_SMEM>>>(
        qth, qtl, kth, ktl, s);

    // P = softmax(S), emitted fp16
    softmax_rows<<<BB * NN, 256>>>(s, ph);

    // out = gamma * (V @ P^T) + x  (fp16 mma, ldmatrix fragments)
    cudaFuncSetAttribute(h_nt_mma_kernel<NN, NN / 32, true>,
                         cudaFuncAttributeMaxDynamicSharedMemorySize, H_SMEM);
    h_nt_mma_kernel<NN, NN / 32, true><<<dim3(NN / 128, CC / 128, BB), blk, H_SMEM>>>(
        vh, ph, x, out, gamma, sX, (long long)NN * NN, sX);
}